// round 3
// baseline (speedup 1.0000x reference)
#include <cuda_runtime.h>
#include <math.h>

#define Bn  65536
#define En  512
#define SLn 128
#define Hn  256
#define NBn 6
#define Dn  640
#define BM  64
#define BK  16

// ---------------- scratch (no allocations allowed) ----------------
__device__ float g_sbuf[(size_t)Bn * SLn];        // speed_in output s [B,128]
__device__ int   g_perm[Bn + NBn * BM];           // padded permutation
__device__ int   g_counts[NBn];
__device__ int   g_cursor[NBn];
__device__ int   g_poff[NBn + 1];                 // 64-aligned segment offsets

// ---------------- bucketing kernels ----------------
__global__ void k_zero() {
    int t = threadIdx.x;
    if (t < NBn) { g_counts[t] = 0; g_cursor[t] = 0; }
}

__global__ void k_count(const int* __restrict__ cmd) {
    __shared__ int loc[NBn];
    if (threadIdx.x < NBn) loc[threadIdx.x] = 0;
    __syncthreads();
    int i = blockIdx.x * blockDim.x + threadIdx.x;
    if (i < Bn) atomicAdd(&loc[cmd[i] - 1], 1);
    __syncthreads();
    if (threadIdx.x < NBn) atomicAdd(&g_counts[threadIdx.x], loc[threadIdx.x]);
}

__global__ void k_scan() {
    int acc = 0;
    for (int g = 0; g < NBn; g++) {
        g_poff[g] = acc;
        acc += (g_counts[g] + BM - 1) & ~(BM - 1);
    }
    g_poff[NBn] = acc;
}

__global__ void k_scatter(const int* __restrict__ cmd) {
    int i = blockIdx.x * blockDim.x + threadIdx.x;
    if (i < Bn) {
        int g = cmd[i] - 1;
        int idx = atomicAdd(&g_cursor[g], 1);
        g_perm[g_poff[g] + idx] = i;
    }
}

// ---------------- speed_in: s = relu(speed*w1+b1) @ W2 + b2 ----------------
__global__ __launch_bounds__(256) void k_speedin(
    const float* __restrict__ speed,
    const float* __restrict__ w1, const float* __restrict__ b1,
    const float* __restrict__ W2, const float* __restrict__ b2)
{
    __shared__ float A_s[BK][BM + 8];
    __shared__ float B_s[BK][SLn];
    __shared__ float w1s[Hn], b1s[Hn];

    int tid  = threadIdx.x;
    int row0 = blockIdx.x * BM;
    w1s[tid] = w1[tid]; b1s[tid] = b1[tid];

    int rg = tid >> 5;        // 0..7 : rows rg*8..+7
    int cg = tid & 31;        // 0..31: cols cg*4..+3
    float acc[8][4];
#pragma unroll
    for (int i = 0; i < 8; i++)
#pragma unroll
        for (int j = 0; j < 4; j++) acc[i][j] = 0.f;

    int arow = tid >> 2;              // 0..63
    int ak   = (tid & 3) * 4;         // 0,4,8,12
    float spd = speed[row0 + arow];
    int bk = tid >> 4;                // 0..15
    int bn = (tid & 15) * 8;          // 0..120

    for (int kt = 0; kt < Hn / BK; ++kt) {
        int kk = kt * BK + ak;
        const float* src = W2 + (size_t)(kt * BK + bk) * SLn + bn;
        float4 v0 = *(const float4*)src;
        float4 v1 = *(const float4*)(src + 4);
        __syncthreads();
#pragma unroll
        for (int j = 0; j < 4; j++) {
            float v = spd * w1s[kk + j] + b1s[kk + j];
            A_s[ak + j][arow] = v > 0.f ? v : 0.f;
        }
        *(float4*)&B_s[bk][bn]     = v0;
        *(float4*)&B_s[bk][bn + 4] = v1;
        __syncthreads();
#pragma unroll
        for (int k = 0; k < BK; k++) {
            float a[8];
            *(float4*)&a[0] = *(const float4*)&A_s[k][rg * 8];
            *(float4*)&a[4] = *(const float4*)&A_s[k][rg * 8 + 4];
            float4 bv = *(const float4*)&B_s[k][cg * 4];
#pragma unroll
            for (int i = 0; i < 8; i++) {
                acc[i][0] += a[i] * bv.x; acc[i][1] += a[i] * bv.y;
                acc[i][2] += a[i] * bv.z; acc[i][3] += a[i] * bv.w;
            }
        }
    }
    float4 bias = *(const float4*)&b2[cg * 4];
#pragma unroll
    for (int i = 0; i < 8; i++) {
        float4 o;
        o.x = acc[i][0] + bias.x; o.y = acc[i][1] + bias.y;
        o.z = acc[i][2] + bias.z; o.w = acc[i][3] + bias.w;
        *(float4*)&g_sbuf[(size_t)(row0 + rg * 8 + i) * SLn + cg * 4] = o;
    }
}

// ---------------- fused branch MLP (gathered rows, per-segment weights) ---
__global__ __launch_bounds__(256) void k_branch(
    const float* __restrict__ emb,
    const float* __restrict__ bW1, const float* __restrict__ bb1,
    const float* __restrict__ bW2, const float* __restrict__ bb2,
    const float* __restrict__ bW3, const float* __restrict__ bb3,
    float* __restrict__ out)
{
    extern __shared__ float sm[];
    float (*A_s)[BM + 8] = (float(*)[BM + 8])sm;                          // 16x72
    float (*B_s)[Hn]     = (float(*)[Hn])(sm + BK * (BM + 8));            // 16x256
    float (*H_s)[Hn + 8] = (float(*)[Hn + 8])(sm + BK * (BM + 8) + BK * Hn); // 64x264
    int*  rows_s = (int*)(sm + BK * (BM + 8) + BK * Hn + BM * (Hn + 8));

    int row0 = blockIdx.x * BM;
    if (row0 >= g_poff[NBn]) return;
    int g = 0;
#pragma unroll
    for (int i = 0; i < NBn - 1; i++) if (row0 >= g_poff[i + 1]) g = i + 1;
    int base = g_poff[g];
    int cnt  = g_counts[g];
    int lr0  = row0 - base;

    int tid = threadIdx.x;
    if (tid < BM) {
        int l = lr0 + tid;
        rows_s[tid] = (l < cnt) ? g_perm[base + l] : -1;
    }
    __syncthreads();

    int rg = tid >> 5, cg = tid & 31;
    int arow = tid >> 2, ak = (tid & 3) * 4;
    int bk = tid >> 4, bn = (tid & 15) * 16;
    int orow = rows_s[arow];

    float acc[8][8];
#pragma unroll
    for (int i = 0; i < 8; i++)
#pragma unroll
        for (int j = 0; j < 8; j++) acc[i][j] = 0.f;

    // ---- layer 1: [64,640] x [640,256] ----
    const float* W1 = bW1 + (size_t)g * Dn * Hn;
    for (int kt = 0; kt < Dn / BK; ++kt) {
        int kk = kt * BK + ak;
        float4 av = make_float4(0.f, 0.f, 0.f, 0.f);
        if (orow >= 0) {
            av = (kk < En) ? *(const float4*)(emb + (size_t)orow * En + kk)
                           : *(const float4*)(g_sbuf + (size_t)orow * SLn + (kk - En));
        }
        const float* src = W1 + (size_t)(kt * BK + bk) * Hn + bn;
        float4 w0 = *(const float4*)src;
        float4 w1v = *(const float4*)(src + 4);
        float4 w2v = *(const float4*)(src + 8);
        float4 w3v = *(const float4*)(src + 12);
        __syncthreads();
        A_s[ak + 0][arow] = av.x; A_s[ak + 1][arow] = av.y;
        A_s[ak + 2][arow] = av.z; A_s[ak + 3][arow] = av.w;
        *(float4*)&B_s[bk][bn]      = w0;  *(float4*)&B_s[bk][bn + 4]  = w1v;
        *(float4*)&B_s[bk][bn + 8]  = w2v; *(float4*)&B_s[bk][bn + 12] = w3v;
        __syncthreads();
#pragma unroll
        for (int k = 0; k < BK; k++) {
            float a[8], b[8];
            *(float4*)&a[0] = *(const float4*)&A_s[k][rg * 8];
            *(float4*)&a[4] = *(const float4*)&A_s[k][rg * 8 + 4];
            *(float4*)&b[0] = *(const float4*)&B_s[k][cg * 8];
            *(float4*)&b[4] = *(const float4*)&B_s[k][cg * 8 + 4];
#pragma unroll
            for (int i = 0; i < 8; i++)
#pragma unroll
                for (int j = 0; j < 8; j++) acc[i][j] += a[i] * b[j];
        }
    }
    {   // bias + relu -> H_s
        float bs[8];
        const float* bias = bb1 + g * Hn + cg * 8;
        *(float4*)&bs[0] = *(const float4*)bias;
        *(float4*)&bs[4] = *(const float4*)(bias + 4);
#pragma unroll
        for (int i = 0; i < 8; i++) {
            float4 o0, o1;
            o0.x = fmaxf(acc[i][0] + bs[0], 0.f); o0.y = fmaxf(acc[i][1] + bs[1], 0.f);
            o0.z = fmaxf(acc[i][2] + bs[2], 0.f); o0.w = fmaxf(acc[i][3] + bs[3], 0.f);
            o1.x = fmaxf(acc[i][4] + bs[4], 0.f); o1.y = fmaxf(acc[i][5] + bs[5], 0.f);
            o1.z = fmaxf(acc[i][6] + bs[6], 0.f); o1.w = fmaxf(acc[i][7] + bs[7], 0.f);
            *(float4*)&H_s[rg * 8 + i][cg * 8]     = o0;
            *(float4*)&H_s[rg * 8 + i][cg * 8 + 4] = o1;
        }
    }
    __syncthreads();

    // ---- layer 2: [64,256] x [256,256] ----
#pragma unroll
    for (int i = 0; i < 8; i++)
#pragma unroll
        for (int j = 0; j < 8; j++) acc[i][j] = 0.f;
    const float* W2 = bW2 + (size_t)g * Hn * Hn;
    for (int kt = 0; kt < Hn / BK; ++kt) {
        const float* src = W2 + (size_t)(kt * BK + bk) * Hn + bn;
        float4 w0 = *(const float4*)src;
        float4 w1v = *(const float4*)(src + 4);
        float4 w2v = *(const float4*)(src + 8);
        float4 w3v = *(const float4*)(src + 12);
        __syncthreads();
        *(float4*)&B_s[bk][bn]      = w0;  *(float4*)&B_s[bk][bn + 4]  = w1v;
        *(float4*)&B_s[bk][bn + 8]  = w2v; *(float4*)&B_s[bk][bn + 12] = w3v;
        __syncthreads();
#pragma unroll
        for (int k = 0; k < BK; k++) {
            float a[8], b[8];
#pragma unroll
            for (int i = 0; i < 8; i++) a[i] = H_s[rg * 8 + i][kt * BK + k];
            *(float4*)&b[0] = *(const float4*)&B_s[k][cg * 8];
            *(float4*)&b[4] = *(const float4*)&B_s[k][cg * 8 + 4];
#pragma unroll
            for (int i = 0; i < 8; i++)
#pragma unroll
                for (int j = 0; j < 8; j++) acc[i][j] += a[i] * b[j];
        }
    }
    __syncthreads();   // all threads done reading H_s before overwrite
    {   // bias + relu -> H_s (h2)
        float bs[8];
        const float* bias = bb2 + g * Hn + cg * 8;
        *(float4*)&bs[0] = *(const float4*)bias;
        *(float4*)&bs[4] = *(const float4*)(bias + 4);
#pragma unroll
        for (int i = 0; i < 8; i++) {
            float4 o0, o1;
            o0.x = fmaxf(acc[i][0] + bs[0], 0.f); o0.y = fmaxf(acc[i][1] + bs[1], 0.f);
            o0.z = fmaxf(acc[i][2] + bs[2], 0.f); o0.w = fmaxf(acc[i][3] + bs[3], 0.f);
            o1.x = fmaxf(acc[i][4] + bs[4], 0.f); o1.y = fmaxf(acc[i][5] + bs[5], 0.f);
            o1.z = fmaxf(acc[i][6] + bs[6], 0.f); o1.w = fmaxf(acc[i][7] + bs[7], 0.f);
            *(float4*)&H_s[rg * 8 + i][cg * 8]     = o0;
            *(float4*)&H_s[rg * 8 + i][cg * 8 + 4] = o1;
        }
    }

    // stage W3 [256,3] into B_s region (768 floats) while H_s settles
    float* W3s = &B_s[0][0];
    {
        const float* W3 = bW3 + (size_t)g * Hn * 3;
        if (tid < 192) {
            *(float4*)&W3s[tid * 4] = *(const float4*)&W3[tid * 4];
        }
    }
    __syncthreads();

    // ---- layer 3: [64,256] x [256,3] + sigmoid + scatter ----
    if (tid < BM * 3) {
        int r = tid / 3, o = tid - r * 3;
        float s = bb3[g * 3 + o];
#pragma unroll 8
        for (int k = 0; k < Hn; k++) s += H_s[r][k] * W3s[k * 3 + o];
        float y = 1.f / (1.f + expf(-s));
        if (lr0 + r < cnt) out[(size_t)rows_s[r] * 3 + o] = y;
    }
}

// ---------------- fused speed head (natural row order) ----------------
__global__ __launch_bounds__(256) void k_speedhead(
    const float* __restrict__ emb,
    const float* __restrict__ W1g, const float* __restrict__ b1g,
    const float* __restrict__ W2g, const float* __restrict__ b2g,
    const float* __restrict__ W3g, const float* __restrict__ b3g,
    float* __restrict__ out)
{
    extern __shared__ float sm[];
    float (*A_s)[BM + 8] = (float(*)[BM + 8])sm;
    float (*B_s)[Hn]     = (float(*)[Hn])(sm + BK * (BM + 8));
    float (*H_s)[Hn + 8] = (float(*)[Hn + 8])(sm + BK * (BM + 8) + BK * Hn);

    int row0 = blockIdx.x * BM;
    int tid = threadIdx.x;
    int rg = tid >> 5, cg = tid & 31;
    int arow = tid >> 2, ak = (tid & 3) * 4;
    int bk = tid >> 4, bn = (tid & 15) * 16;
    int orow = row0 + arow;

    float acc[8][8];
#pragma unroll
    for (int i = 0; i < 8; i++)
#pragma unroll
        for (int j = 0; j < 8; j++) acc[i][j] = 0.f;

    for (int kt = 0; kt < Dn / BK; ++kt) {
        int kk = kt * BK + ak;
        float4 av = (kk < En) ? *(const float4*)(emb + (size_t)orow * En + kk)
                              : *(const float4*)(g_sbuf + (size_t)orow * SLn + (kk - En));
        const float* src = W1g + (size_t)(kt * BK + bk) * Hn + bn;
        float4 w0 = *(const float4*)src;
        float4 w1v = *(const float4*)(src + 4);
        float4 w2v = *(const float4*)(src + 8);
        float4 w3v = *(const float4*)(src + 12);
        __syncthreads();
        A_s[ak + 0][arow] = av.x; A_s[ak + 1][arow] = av.y;
        A_s[ak + 2][arow] = av.z; A_s[ak + 3][arow] = av.w;
        *(float4*)&B_s[bk][bn]      = w0;  *(float4*)&B_s[bk][bn + 4]  = w1v;
        *(float4*)&B_s[bk][bn + 8]  = w2v; *(float4*)&B_s[bk][bn + 12] = w3v;
        __syncthreads();
#pragma unroll
        for (int k = 0; k < BK; k++) {
            float a[8], b[8];
            *(float4*)&a[0] = *(const float4*)&A_s[k][rg * 8];
            *(float4*)&a[4] = *(const float4*)&A_s[k][rg * 8 + 4];
            *(float4*)&b[0] = *(const float4*)&B_s[k][cg * 8];
            *(float4*)&b[4] = *(const float4*)&B_s[k][cg * 8 + 4];
#pragma unroll
            for (int i = 0; i < 8; i++)
#pragma unroll
                for (int j = 0; j < 8; j++) acc[i][j] += a[i] * b[j];
        }
    }
    {
        float bs[8];
        const float* bias = b1g + cg * 8;
        *(float4*)&bs[0] = *(const float4*)bias;
        *(float4*)&bs[4] = *(const float4*)(bias + 4);
#pragma unroll
        for (int i = 0; i < 8; i++) {
            float4 o0, o1;
            o0.x = fmaxf(acc[i][0] + bs[0], 0.f); o0.y = fmaxf(acc[i][1] + bs[1], 0.f);
            o0.z = fmaxf(acc[i][2] + bs[2], 0.f); o0.w = fmaxf(acc[i][3] + bs[3], 0.f);
            o1.x = fmaxf(acc[i][4] + bs[4], 0.f); o1.y = fmaxf(acc[i][5] + bs[5], 0.f);
            o1.z = fmaxf(acc[i][6] + bs[6], 0.f); o1.w = fmaxf(acc[i][7] + bs[7], 0.f);
            *(float4*)&H_s[rg * 8 + i][cg * 8]     = o0;
            *(float4*)&H_s[rg * 8 + i][cg * 8 + 4] = o1;
        }
    }
    __syncthreads();

#pragma unroll
    for (int i = 0; i < 8; i++)
#pragma unroll
        for (int j = 0; j < 8; j++) acc[i][j] = 0.f;
    for (int kt = 0; kt < Hn / BK; ++kt) {
        const float* src = W2g + (size_t)(kt * BK + bk) * Hn + bn;
        float4 w0 = *(const float4*)src;
        float4 w1v = *(const float4*)(src + 4);
        float4 w2v = *(const float4*)(src + 8);
        float4 w3v = *(const float4*)(src + 12);
        __syncthreads();
        *(float4*)&B_s[bk][bn]      = w0;  *(float4*)&B_s[bk][bn + 4]  = w1v;
        *(float4*)&B_s[bk][bn + 8]  = w2v; *(float4*)&B_s[bk][bn + 12] = w3v;
        __syncthreads();
#pragma unroll
        for (int k = 0; k < BK; k++) {
            float a[8], b[8];
#pragma unroll
            for (int i = 0; i < 8; i++) a[i] = H_s[rg * 8 + i][kt * BK + k];
            *(float4*)&b[0] = *(const float4*)&B_s[k][cg * 8];
            *(float4*)&b[4] = *(const float4*)&B_s[k][cg * 8 + 4];
#pragma unroll
            for (int i = 0; i < 8; i++)
#pragma unroll
                for (int j = 0; j < 8; j++) acc[i][j] += a[i] * b[j];
        }
    }
    __syncthreads();
    {
        float bs[8];
        const float* bias = b2g + cg * 8;
        *(float4*)&bs[0] = *(const float4*)bias;
        *(float4*)&bs[4] = *(const float4*)(bias + 4);
#pragma unroll
        for (int i = 0; i < 8; i++) {
            float4 o0, o1;
            o0.x = fmaxf(acc[i][0] + bs[0], 0.f); o0.y = fmaxf(acc[i][1] + bs[1], 0.f);
            o0.z = fmaxf(acc[i][2] + bs[2], 0.f); o0.w = fmaxf(acc[i][3] + bs[3], 0.f);
            o1.x = fmaxf(acc[i][4] + bs[4], 0.f); o1.y = fmaxf(acc[i][5] + bs[5], 0.f);
            o1.z = fmaxf(acc[i][6] + bs[6], 0.f); o1.w = fmaxf(acc[i][7] + bs[7], 0.f);
            *(float4*)&H_s[rg * 8 + i][cg * 8]     = o0;
            *(float4*)&H_s[rg * 8 + i][cg * 8 + 4] = o1;
        }
    }

    // stage W3 [256] into B_s region
    float* W3s = &B_s[0][0];
    if (tid < Hn / 4) *(float4*)&W3s[tid * 4] = *(const float4*)&W3g[tid * 4];
    __syncthreads();

    if (tid < BM) {
        int r = tid;
        float s = b3g[0];
#pragma unroll 8
        for (int k = 0; k < Hn; k++) s += H_s[r][k] * W3s[k];
        out[(size_t)Bn * 3 + row0 + r] = s;
    }
}

// ---------------- launcher ----------------
extern "C" void kernel_launch(void* const* d_in, const int* in_sizes, int n_in,
                              void* d_out, int out_size) {
    const float* embedding = (const float*)d_in[0];
    const float* speed     = (const float*)d_in[1];
    const int*   command   = (const int*)d_in[2];
    const float* si_W1 = (const float*)d_in[3];
    const float* si_b1 = (const float*)d_in[4];
    const float* si_W2 = (const float*)d_in[5];
    const float* si_b2 = (const float*)d_in[6];
    const float* bW1   = (const float*)d_in[7];
    const float* bb1   = (const float*)d_in[8];
    const float* bW2   = (const float*)d_in[9];
    const float* bb2   = (const float*)d_in[10];
    const float* bW3   = (const float*)d_in[11];
    const float* bb3   = (const float*)d_in[12];
    const float* so_W1 = (const float*)d_in[13];
    const float* so_b1 = (const float*)d_in[14];
    const float* so_W2 = (const float*)d_in[15];
    const float* so_b2 = (const float*)d_in[16];
    const float* so_W3 = (const float*)d_in[17];
    const float* so_b3 = (const float*)d_in[18];
    float* out = (float*)d_out;

    int smem_bytes = (BK * (BM + 8) + BK * Hn + BM * (Hn + 8)) * 4 + BM * 4;
    cudaFuncSetAttribute(k_branch, cudaFuncAttributeMaxDynamicSharedMemorySize, smem_bytes);
    cudaFuncSetAttribute(k_speedhead, cudaFuncAttributeMaxDynamicSharedMemorySize, smem_bytes);

    k_zero<<<1, 32>>>();
    k_count<<<Bn / 256, 256>>>(command);
    k_scan<<<1, 1>>>();
    k_scatter<<<Bn / 256, 256>>>(command);
    k_speedin<<<Bn / BM, 256>>>(speed, si_W1, si_b1, si_W2, si_b2);

    int branch_tiles = (Bn + NBn * (BM - 1)) / BM + 1;   // 1030, covers padding
    k_branch<<<branch_tiles, 256, smem_bytes>>>(embedding, bW1, bb1, bW2, bb2, bW3, bb3, out);
    k_speedhead<<<Bn / BM, 256, smem_bytes>>>(embedding, so_W1, so_b1, so_W2, so_b2, so_W3, so_b3, out);
}

// round 5
// speedup vs baseline: 4.5878x; 4.5878x over previous
#include <cuda_runtime.h>
#include <cuda_bf16.h>
#include <math.h>
#include <stdint.h>

#define Bn  65536
#define En  512
#define SLn 128
#define Hn  256
#define NBn 6
#define Dn  640
#define TM  128

// ---------------- scratch (static device globals; no allocations) ---------
__device__ float g_sbuf[(size_t)Bn * SLn];
__device__ int   g_perm[Bn + NBn * TM];
__device__ int   g_counts[NBn];
__device__ int   g_cursor[NBn];
__device__ int   g_poff[NBn + 1];
__device__ __align__(16) unsigned short g_Ahi[(size_t)Bn * Dn];
__device__ __align__(16) unsigned short g_Alo[(size_t)Bn * Dn];
__device__ __align__(16) unsigned short g_W1hi[7 * 256 * Dn];
__device__ __align__(16) unsigned short g_W1lo[7 * 256 * Dn];
__device__ __align__(16) unsigned short g_W2hi[7 * 256 * Hn];
__device__ __align__(16) unsigned short g_W2lo[7 * 256 * Hn];

// ---------------- helpers ----------------
__device__ __forceinline__ uint32_t smem_u32(const void* p) {
    uint32_t a;
    asm("{ .reg .u64 t; cvta.to.shared.u64 t, %1; cvt.u32.u64 %0, t; }" : "=r"(a) : "l"(p));
    return a;
}
__device__ __forceinline__ void cpa16(uint32_t dst, const void* src, int sz) {
    asm volatile("cp.async.cg.shared.global [%0], [%1], 16, %2;"
                 :: "r"(dst), "l"(src), "r"(sz) : "memory");
}
#define CP_COMMIT() asm volatile("cp.async.commit_group;" ::: "memory")
#define CP_WAIT(n)  asm volatile("cp.async.wait_group %0;" :: "n"(n) : "memory")

__device__ __forceinline__ void mma16816(float* d,
    uint32_t a0, uint32_t a1, uint32_t a2, uint32_t a3,
    uint32_t b0, uint32_t b1) {
    asm volatile(
        "mma.sync.aligned.m16n8k16.row.col.f32.bf16.bf16.f32 "
        "{%0,%1,%2,%3}, {%4,%5,%6,%7}, {%8,%9}, {%0,%1,%2,%3};"
        : "+f"(d[0]), "+f"(d[1]), "+f"(d[2]), "+f"(d[3])
        : "r"(a0), "r"(a1), "r"(a2), "r"(a3), "r"(b0), "r"(b1));
}

#define SWZ(x)  ((x) ^ (((x) >> 3) & 0x70))   // 128B rows
#define SWZ2(x) ((x) ^ (((x) >> 5) & 0x70))   // 512B rows

__device__ __forceinline__ unsigned short f2bf(float x) {
    unsigned short u; asm("cvt.rn.bf16.f32 %0, %1;" : "=h"(u) : "f"(x)); return u;
}
__device__ __forceinline__ float bf2f(unsigned short u) {
    return __uint_as_float(((uint32_t)u) << 16);
}
__device__ __forceinline__ void split2(float x, unsigned short& h, unsigned short& l) {
    h = f2bf(x);
    l = f2bf(x - bf2f(h));
}

// ---------------- bucketing ----------------
__global__ void k_zero() {
    int t = threadIdx.x;
    if (t < NBn) { g_counts[t] = 0; g_cursor[t] = 0; }
}
__global__ void k_count(const int* __restrict__ cmd) {
    __shared__ int loc[NBn];
    if (threadIdx.x < NBn) loc[threadIdx.x] = 0;
    __syncthreads();
    int i = blockIdx.x * blockDim.x + threadIdx.x;
    if (i < Bn) atomicAdd(&loc[cmd[i] - 1], 1);
    __syncthreads();
    if (threadIdx.x < NBn) atomicAdd(&g_counts[threadIdx.x], loc[threadIdx.x]);
}
__global__ void k_scan() {
    int acc = 0;
    for (int g = 0; g < NBn; g++) {
        g_poff[g] = acc;
        acc += (g_counts[g] + TM - 1) & ~(TM - 1);
    }
    g_poff[NBn] = acc;
}
__global__ void k_scatter(const int* __restrict__ cmd) {
    int i = blockIdx.x * blockDim.x + threadIdx.x;
    if (i < Bn) {
        int g = cmd[i] - 1;
        int idx = atomicAdd(&g_cursor[g], 1);
        g_perm[g_poff[g] + idx] = i;
    }
}

// ---------------- speed_in (fp32 SIMT) ----------------
__global__ __launch_bounds__(256) void k_speedin(
    const float* __restrict__ speed,
    const float* __restrict__ w1, const float* __restrict__ b1,
    const float* __restrict__ W2, const float* __restrict__ b2)
{
    __shared__ float A_s[16][72];
    __shared__ float B_s[16][SLn];
    __shared__ float w1s[Hn], b1s[Hn];
    int tid = threadIdx.x;
    int row0 = blockIdx.x * 64;
    w1s[tid] = w1[tid]; b1s[tid] = b1[tid];
    int rg = tid >> 5, cg = tid & 31;
    float acc[8][4];
#pragma unroll
    for (int i = 0; i < 8; i++)
#pragma unroll
        for (int j = 0; j < 4; j++) acc[i][j] = 0.f;
    int arow = tid >> 2, ak = (tid & 3) * 4;
    float spd = speed[row0 + arow];
    int bk = tid >> 4, bnn = (tid & 15) * 8;
    for (int kt = 0; kt < Hn / 16; ++kt) {
        int kk = kt * 16 + ak;
        const float* src = W2 + (size_t)(kt * 16 + bk) * SLn + bnn;
        float4 v0 = *(const float4*)src;
        float4 v1 = *(const float4*)(src + 4);
        __syncthreads();
#pragma unroll
        for (int j = 0; j < 4; j++) {
            float v = spd * w1s[kk + j] + b1s[kk + j];
            A_s[ak + j][arow] = v > 0.f ? v : 0.f;
        }
        *(float4*)&B_s[bk][bnn] = v0;
        *(float4*)&B_s[bk][bnn + 4] = v1;
        __syncthreads();
#pragma unroll
        for (int k = 0; k < 16; k++) {
            float a[8];
            *(float4*)&a[0] = *(const float4*)&A_s[k][rg * 8];
            *(float4*)&a[4] = *(const float4*)&A_s[k][rg * 8 + 4];
            float4 bv = *(const float4*)&B_s[k][cg * 4];
#pragma unroll
            for (int i = 0; i < 8; i++) {
                acc[i][0] += a[i] * bv.x; acc[i][1] += a[i] * bv.y;
                acc[i][2] += a[i] * bv.z; acc[i][3] += a[i] * bv.w;
            }
        }
    }
    float4 bias = *(const float4*)&b2[cg * 4];
#pragma unroll
    for (int i = 0; i < 8; i++) {
        float4 o;
        o.x = acc[i][0] + bias.x; o.y = acc[i][1] + bias.y;
        o.z = acc[i][2] + bias.z; o.w = acc[i][3] + bias.w;
        *(float4*)&g_sbuf[(size_t)(row0 + rg * 8 + i) * SLn + cg * 4] = o;
    }
}

// ---------------- convert A rows (emb || s) -> bf16 hi/lo [B,640] ---------
__global__ __launch_bounds__(256) void k_convA(const float* __restrict__ emb) {
    size_t quad = (size_t)blockIdx.x * 256 + threadIdx.x;
    size_t b = quad / 160;
    int d0 = (int)(quad - b * 160) * 4;
    float4 v = (d0 < En) ? *(const float4*)(emb + b * En + d0)
                         : *(const float4*)(g_sbuf + b * SLn + (d0 - En));
    unsigned short h0, h1, h2, h3, l0, l1, l2, l3;
    split2(v.x, h0, l0); split2(v.y, h1, l1);
    split2(v.z, h2, l2); split2(v.w, h3, l3);
    uint2 H, L;
    H.x = ((uint32_t)h1 << 16) | h0; H.y = ((uint32_t)h3 << 16) | h2;
    L.x = ((uint32_t)l1 << 16) | l0; L.y = ((uint32_t)l3 << 16) | l2;
    *(uint2*)&g_Ahi[b * Dn + d0] = H;
    *(uint2*)&g_Alo[b * Dn + d0] = L;
}

// -------- transpose + convert weights: [Kd,256] -> [7][256][Kd] hi/lo -----
__global__ __launch_bounds__(256) void k_convW(
    const float* __restrict__ srcB, const float* __restrict__ srcS,
    unsigned short* __restrict__ dhi, unsigned short* __restrict__ dlo, int Kd)
{
    __shared__ float tile[32][33];
    int ntk = Kd / 32;
    int bid = blockIdx.x;
    int g = bid / (ntk * 8);
    int rem = bid - g * ntk * 8;
    int kt = rem / 8, nt = rem - (rem / 8) * 8;
    const float* src = (g < 6) ? srcB + (size_t)g * Kd * 256 : srcS;
    int tid = threadIdx.x;
#pragma unroll
    for (int i = 0; i < 4; i++) {
        int idx = i * 256 + tid;
        int kk = idx >> 5, nn = idx & 31;
        tile[kk][nn] = src[(size_t)(kt * 32 + kk) * 256 + nt * 32 + nn];
    }
    __syncthreads();
#pragma unroll
    for (int i = 0; i < 4; i++) {
        int idx = i * 256 + tid;
        int nn = idx >> 5, kk = idx & 31;
        float x = tile[kk][nn];
        unsigned short h, l; split2(x, h, l);
        size_t o = ((size_t)g * 256 + nt * 32 + nn) * Kd + kt * 32 + kk;
        dhi[o] = h; dlo[o] = l;
    }
}

// ---------------- fused MLP via mma.sync (HMMA, base ISA) ----------------
// smem layout
#define S_STG(s) ((uint32_t)(s) * 98304u)
#define S_AHI(s) (S_STG(s))
#define S_ALO(s) (S_STG(s) + 16384u)
#define S_BHI(s) (S_STG(s) + 32768u)
#define S_BLO(s) (S_STG(s) + 65536u)
#define S_A2HI   0u
#define S_A2LO   65536u
#define S_B2HI   131072u
#define S_B2LO   163840u
#define S_BIAS1  196608u
#define S_BIAS2  197632u
#define S_W3     198656u
#define S_B3     201728u
#define S_ROWS   201744u
#define S_SRED   202256u
#define SMEM_TOT 203808

__global__ __launch_bounds__(512, 1) void k_mlp(
    const float* __restrict__ bb1, const float* __restrict__ bb2,
    const float* __restrict__ bW3, const float* __restrict__ bb3,
    const float* __restrict__ so_b1, const float* __restrict__ so_b2,
    const float* __restrict__ so_W3, const float* __restrict__ so_b3,
    float* __restrict__ out)
{
    extern __shared__ unsigned char sm[];
    int tid = threadIdx.x;
    int wid = tid >> 5, lane = tid & 31;
    int wm = wid & 3, wn = wid >> 2;
    int bid = blockIdx.x;
    bool is_speed = (bid < Bn / TM);
    int g, row0;
    if (is_speed) { g = 6; row0 = bid * TM; }
    else {
        int t = bid - Bn / TM;
        row0 = t * TM;
        if (row0 >= g_poff[NBn]) return;
        g = 0;
#pragma unroll
        for (int i = 0; i < NBn - 1; i++) if (row0 >= g_poff[i + 1]) g = i + 1;
    }
    uint32_t sb = smem_u32(sm);
    float* bias1s = (float*)(sm + S_BIAS1);
    float* bias2s = (float*)(sm + S_BIAS2);
    float* w3s    = (float*)(sm + S_W3);
    float* b3s    = (float*)(sm + S_B3);
    int*   rows_s = (int*)(sm + S_ROWS);
    float* sred   = (float*)(sm + S_SRED);

    // metadata
    if (tid < TM) {
        if (is_speed) rows_s[tid] = row0 + tid;
        else {
            int base = g_poff[g], cnt = g_counts[g];
            int l = row0 - base + tid;
            rows_s[tid] = (l < cnt) ? g_perm[base + l] : -1;
        }
    }
    if (tid < Hn) {
        bias1s[tid] = is_speed ? so_b1[tid] : bb1[g * Hn + tid];
        bias2s[tid] = is_speed ? so_b2[tid] : bb2[g * Hn + tid];
    }
    if (is_speed) { if (tid < Hn) w3s[tid] = so_W3[tid]; }
    else { for (int i = tid; i < Hn * 3; i += 512) w3s[i] = bW3[g * Hn * 3 + i]; }
    if (tid < (is_speed ? 1 : 3)) b3s[tid] = is_speed ? so_b3[0] : bb3[g * 3 + tid];
    if (tid < TM * 3) sred[tid] = 0.f;
    __syncthreads();

    // ---- staging lambdas (manually inlined) ----
    // layer-1 stage fill for chunk c into stage s
    auto fill1 = [&](int s, int c) {
        // A hi/lo: 128 rows x 8 units each
#pragma unroll
        for (int it = 0; it < 2; ++it) {
            int idx = it * 512 + tid;
            int r = idx >> 3, seg = idx & 7;
            int orow = rows_s[r];
            const unsigned short* sh = g_Ahi;
            const unsigned short* sl = g_Alo;
            size_t go = (orow >= 0) ? ((size_t)orow * Dn + c * 64 + seg * 8) : 0;
            int sz = (orow >= 0) ? 16 : 0;
            uint32_t sw = SWZ((uint32_t)(r * 128 + seg * 16));
            cpa16(sb + S_AHI(s) + sw, sh + go, sz);
            cpa16(sb + S_ALO(s) + sw, sl + go, sz);
        }
        // B hi/lo: 256 rows x 8 units
#pragma unroll
        for (int it = 0; it < 4; ++it) {
            int idx = it * 512 + tid;
            int n = idx >> 3, seg = idx & 7;
            size_t go = ((size_t)g * 256 + n) * Dn + c * 64 + seg * 8;
            uint32_t sw = SWZ((uint32_t)(n * 128 + seg * 16));
            cpa16(sb + S_BHI(s) + sw, g_W1hi + go, 16);
            cpa16(sb + S_BLO(s) + sw, g_W1lo + go, 16);
        }
        CP_COMMIT();
    };
    auto fill2 = [&](int c2) {
#pragma unroll
        for (int it = 0; it < 4; ++it) {
            int idx = it * 512 + tid;
            int n = idx >> 3, seg = idx & 7;
            size_t go = ((size_t)g * 256 + n) * Hn + c2 * 64 + seg * 8;
            uint32_t sw = SWZ((uint32_t)(n * 128 + seg * 16));
            cpa16(sb + S_B2HI + sw, g_W2hi + go, 16);
            cpa16(sb + S_B2LO + sw, g_W2lo + go, 16);
        }
        CP_COMMIT();
    };

    float acc[2][8][4];
#pragma unroll
    for (int m = 0; m < 2; m++)
#pragma unroll
        for (int n = 0; n < 8; n++)
#pragma unroll
            for (int j = 0; j < 4; j++) acc[m][n][j] = 0.f;

    // ================= layer 1: 10 chunks of k=64, double-buffered =========
    fill1(0, 0);
    fill1(1, 1);
    for (int c = 0; c < 10; ++c) {
        int s = c & 1;
        if (c < 9) { CP_WAIT(1); } else { CP_WAIT(0); }
        __syncthreads();
        uint32_t aHiB = S_AHI(s), aLoB = S_ALO(s);
        uint32_t bHiB = S_BHI(s), bLoB = S_BLO(s);
#pragma unroll
        for (int ks = 0; ks < 4; ++ks) {
            uint32_t cb = (uint32_t)(ks * 32 + (lane & 3) * 4);
            uint32_t ah[2][4], al[2][4];
#pragma unroll
            for (int m = 0; m < 2; m++) {
                uint32_t r = (uint32_t)(wm * 32 + m * 16 + (lane >> 2));
                uint32_t o0 = SWZ(r * 128 + cb);
                uint32_t o1 = SWZ((r + 8) * 128 + cb);
                uint32_t o2 = SWZ(r * 128 + cb + 16);
                uint32_t o3 = SWZ((r + 8) * 128 + cb + 16);
                ah[m][0] = *(uint32_t*)(sm + aHiB + o0);
                ah[m][1] = *(uint32_t*)(sm + aHiB + o1);
                ah[m][2] = *(uint32_t*)(sm + aHiB + o2);
                ah[m][3] = *(uint32_t*)(sm + aHiB + o3);
                al[m][0] = *(uint32_t*)(sm + aLoB + o0);
                al[m][1] = *(uint32_t*)(sm + aLoB + o1);
                al[m][2] = *(uint32_t*)(sm + aLoB + o2);
                al[m][3] = *(uint32_t*)(sm + aLoB + o3);
            }
#pragma unroll
            for (int nt = 0; nt < 8; ++nt) {
                uint32_t n = (uint32_t)(wn * 64 + nt * 8 + (lane >> 2));
                uint32_t p0 = SWZ(n * 128 + cb), p1 = SWZ(n * 128 + cb + 16);
                uint32_t bh0 = *(uint32_t*)(sm + bHiB + p0);
                uint32_t bh1 = *(uint32_t*)(sm + bHiB + p1);
                uint32_t bl0 = *(uint32_t*)(sm + bLoB + p0);
                uint32_t bl1 = *(uint32_t*)(sm + bLoB + p1);
#pragma unroll
                for (int m = 0; m < 2; m++) {
                    mma16816(acc[m][nt], ah[m][0], ah[m][1], ah[m][2], ah[m][3], bh0, bh1);
                    mma16816(acc[m][nt], ah[m][0], ah[m][1], ah[m][2], ah[m][3], bl0, bl1);
                    mma16816(acc[m][nt], al[m][0], al[m][1], al[m][2], al[m][3], bh0, bh1);
                }
            }
        }
        __syncthreads();
        if (c + 2 < 10) fill1(s, c + 2);
    }

    // issue B2 chunk 0 before epilogue (disjoint smem regions)
    fill2(0);

    // ===== epilogue 1: relu(D+b1) -> bf16 hi/lo into A2 (512B rows, SWZ2) ==
#pragma unroll
    for (int m = 0; m < 2; m++) {
#pragma unroll
        for (int half = 0; half < 2; half++) {
            uint32_t r = (uint32_t)(wm * 32 + m * 16 + half * 8 + (lane >> 2));
#pragma unroll
            for (int nt = 0; nt < 8; ++nt) {
                int c0 = wn * 64 + nt * 8 + (lane & 3) * 2;
                float v0 = acc[m][nt][half * 2 + 0] + bias1s[c0];
                float v1 = acc[m][nt][half * 2 + 1] + bias1s[c0 + 1];
                v0 = fmaxf(v0, 0.f); v1 = fmaxf(v1, 0.f);
                unsigned short h0, h1, l0, l1;
                split2(v0, h0, l0); split2(v1, h1, l1);
                uint32_t byte = SWZ2((uint32_t)(r * 512 + c0 * 2));
                *(uint32_t*)(sm + S_A2HI + byte) = ((uint32_t)h1 << 16) | h0;
                *(uint32_t*)(sm + S_A2LO + byte) = ((uint32_t)l1 << 16) | l0;
            }
        }
    }
#pragma unroll
    for (int m = 0; m < 2; m++)
#pragma unroll
        for (int n = 0; n < 8; n++)
#pragma unroll
            for (int j = 0; j < 4; j++) acc[m][n][j] = 0.f;

    // ================= layer 2: 4 chunks of k=64 ===========================
    for (int c2 = 0; c2 < 4; ++c2) {
        CP_WAIT(0);
        __syncthreads();
#pragma unroll
        for (int ks = 0; ks < 4; ++ks) {
            uint32_t kg = (uint32_t)(c2 * 64 + ks * 16 + (lane & 3) * 2) * 2;
            uint32_t cb = (uint32_t)(ks * 32 + (lane & 3) * 4);
            uint32_t ah[2][4], al[2][4];
#pragma unroll
            for (int m = 0; m < 2; m++) {
                uint32_t r = (uint32_t)(wm * 32 + m * 16 + (lane >> 2));
                uint32_t o0 = SWZ2(r * 512 + kg);
                uint32_t o1 = SWZ2((r + 8) * 512 + kg);
                uint32_t o2 = SWZ2(r * 512 + kg + 16);
                uint32_t o3 = SWZ2((r + 8) * 512 + kg + 16);
                ah[m][0] = *(uint32_t*)(sm + S_A2HI + o0);
                ah[m][1] = *(uint32_t*)(sm + S_A2HI + o1);
                ah[m][2] = *(uint32_t*)(sm + S_A2HI + o2);
                ah[m][3] = *(uint32_t*)(sm + S_A2HI + o3);
                al[m][0] = *(uint32_t*)(sm + S_A2LO + o0);
                al[m][1] = *(uint32_t*)(sm + S_A2LO + o1);
                al[m][2] = *(uint32_t*)(sm + S_A2LO + o2);
                al[m][3] = *(uint32_t*)(sm + S_A2LO + o3);
            }
#pragma unroll
            for (int nt = 0; nt < 8; ++nt) {
                uint32_t n = (uint32_t)(wn * 64 + nt * 8 + (lane >> 2));
                uint32_t p0 = SWZ(n * 128 + cb), p1 = SWZ(n * 128 + cb + 16);
                uint32_t bh0 = *(uint32_t*)(sm + S_B2HI + p0);
                uint32_t bh1 = *(uint32_t*)(sm + S_B2HI + p1);
                uint32_t bl0 = *(uint32_t*)(sm + S_B2LO + p0);
                uint32_t bl1 = *(uint32_t*)(sm + S_B2LO + p1);
#pragma unroll
                for (int m = 0; m < 2; m++) {
                    mma16816(acc[m][nt], ah[m][0], ah[m][1], ah[m][2], ah[m][3], bh0, bh1);
                    mma16816(acc[m][nt], ah[m][0], ah[m][1], ah[m][2], ah[m][3], bl0, bl1);
                    mma16816(acc[m][nt], al[m][0], al[m][1], al[m][2], al[m][3], bh0, bh1);
                }
            }
        }
        __syncthreads();
        if (c2 + 1 < 4) fill2(c2 + 1);
    }

    // ===== epilogue 2: relu(D+b2), layer-3 dot, reduce, activate, scatter ==
#pragma unroll
    for (int m = 0; m < 2; m++) {
#pragma unroll
        for (int half = 0; half < 2; half++) {
            int rl = wm * 32 + m * 16 + half * 8 + (lane >> 2);
            float p0 = 0.f, p1 = 0.f, p2 = 0.f;
#pragma unroll
            for (int nt = 0; nt < 8; ++nt) {
                int c0 = wn * 64 + nt * 8 + (lane & 3) * 2;
                float v0 = fmaxf(acc[m][nt][half * 2 + 0] + bias2s[c0], 0.f);
                float v1 = fmaxf(acc[m][nt][half * 2 + 1] + bias2s[c0 + 1], 0.f);
                if (is_speed) {
                    p0 += v0 * w3s[c0] + v1 * w3s[c0 + 1];
                } else {
                    p0 += v0 * w3s[c0 * 3]     + v1 * w3s[(c0 + 1) * 3];
                    p1 += v0 * w3s[c0 * 3 + 1] + v1 * w3s[(c0 + 1) * 3 + 1];
                    p2 += v0 * w3s[c0 * 3 + 2] + v1 * w3s[(c0 + 1) * 3 + 2];
                }
            }
            // reduce over lane&3 (same row)
#pragma unroll
            for (int d = 1; d < 4; d <<= 1) {
                p0 += __shfl_xor_sync(0xffffffffu, p0, d);
                p1 += __shfl_xor_sync(0xffffffffu, p1, d);
                p2 += __shfl_xor_sync(0xffffffffu, p2, d);
            }
            if ((lane & 3) == 0) {
                if (is_speed) atomicAdd(&sred[rl], p0);
                else {
                    atomicAdd(&sred[rl * 3 + 0], p0);
                    atomicAdd(&sred[rl * 3 + 1], p1);
                    atomicAdd(&sred[rl * 3 + 2], p2);
                }
            }
        }
    }
    __syncthreads();
    if (tid < TM) {
        int orow = rows_s[tid];
        if (is_speed) {
            out[(size_t)Bn * 3 + orow] = sred[tid] + b3s[0];
        } else if (orow >= 0) {
            float s0 = sred[tid * 3 + 0] + b3s[0];
            float s1 = sred[tid * 3 + 1] + b3s[1];
            float s2 = sred[tid * 3 + 2] + b3s[2];
            out[(size_t)orow * 3 + 0] = 1.f / (1.f + expf(-s0));
            out[(size_t)orow * 3 + 1] = 1.f / (1.f + expf(-s1));
            out[(size_t)orow * 3 + 2] = 1.f / (1.f + expf(-s2));
        }
    }
}

// ---------------- launcher ----------------
extern "C" void kernel_launch(void* const* d_in, const int* in_sizes, int n_in,
                              void* d_out, int out_size) {
    const float* embedding = (const float*)d_in[0];
    const float* speed     = (const float*)d_in[1];
    const int*   command   = (const int*)d_in[2];
    const float* si_W1 = (const float*)d_in[3];
    const float* si_b1 = (const float*)d_in[4];
    const float* si_W2 = (const float*)d_in[5];
    const float* si_b2 = (const float*)d_in[6];
    const float* bW1   = (const float*)d_in[7];
    const float* bb1   = (const float*)d_in[8];
    const float* bW2   = (const float*)d_in[9];
    const float* bb2   = (const float*)d_in[10];
    const float* bW3   = (const float*)d_in[11];
    const float* bb3   = (const float*)d_in[12];
    const float* so_W1 = (const float*)d_in[13];
    const float* so_b1 = (const float*)d_in[14];
    const float* so_W2 = (const float*)d_in[15];
    const float* so_b2 = (const float*)d_in[16];
    const float* so_W3 = (const float*)d_in[17];
    const float* so_b3 = (const float*)d_in[18];
    float* out = (float*)d_out;

    unsigned short *w1hi, *w1lo, *w2hi, *w2lo;
    cudaGetSymbolAddress((void**)&w1hi, g_W1hi);
    cudaGetSymbolAddress((void**)&w1lo, g_W1lo);
    cudaGetSymbolAddress((void**)&w2hi, g_W2hi);
    cudaGetSymbolAddress((void**)&w2lo, g_W2lo);

    cudaFuncSetAttribute(k_mlp, cudaFuncAttributeMaxDynamicSharedMemorySize, SMEM_TOT);

    k_zero<<<1, 32>>>();
    k_count<<<Bn / 256, 256>>>(command);
    k_scan<<<1, 1>>>();
    k_scatter<<<Bn / 256, 256>>>(command);
    k_speedin<<<Bn / 64, 256>>>(speed, si_W1, si_b1, si_W2, si_b2);
    k_convA<<<(int)(((size_t)Bn * Dn / 4) / 256), 256>>>(embedding);
    k_convW<<<7 * (Dn / 32) * 8, 256>>>(bW1, so_W1, w1hi, w1lo, Dn);
    k_convW<<<7 * (Hn / 32) * 8, 256>>>(bW2, so_W2, w2hi, w2lo, Hn);

    int branch_tiles = (Bn + NBn * (TM - 1)) / TM + 1;   // 518
    k_mlp<<<Bn / TM + branch_tiles, 512, SMEM_TOT>>>(
        bb1, bb2, bW3, bb3, so_b1, so_b2, so_W3, so_b3, out);
}

// round 8
// speedup vs baseline: 4.6216x; 1.0074x over previous
#include <cuda_runtime.h>
#include <cuda_bf16.h>
#include <math.h>
#include <stdint.h>

#define Bn  65536
#define En  512
#define SLn 128
#define Hn  256
#define NBn 6
#define Dn  640
#define TM  128

// ---------------- scratch (static device globals; no allocations) ---------
__device__ int   g_perm[Bn + NBn * TM];
__device__ int   g_counts[NBn];
__device__ int   g_cursor[NBn];
__device__ int   g_poff[NBn + 1];
__device__ float g_thr[256];             // sorted relu breakpoints of speed_in
__device__ float g_pw[257 * 256];        // per-interval [u(128) | v(128)]
__device__ __align__(16) unsigned short g_Ahi[(size_t)Bn * Dn];
__device__ __align__(16) unsigned short g_Alo[(size_t)Bn * Dn];
__device__ __align__(16) unsigned short g_W1hi[7 * 256 * Dn];
__device__ __align__(16) unsigned short g_W1lo[7 * 256 * Dn];
__device__ __align__(16) unsigned short g_W2hi[7 * 256 * Hn];
__device__ __align__(16) unsigned short g_W2lo[7 * 256 * Hn];

// ---------------- helpers ----------------
__device__ __forceinline__ uint32_t smem_u32(const void* p) {
    uint32_t a;
    asm("{ .reg .u64 t; cvta.to.shared.u64 t, %1; cvt.u32.u64 %0, t; }" : "=r"(a) : "l"(p));
    return a;
}
__device__ __forceinline__ void cpa16(uint32_t dst, const void* src, int sz) {
    asm volatile("cp.async.cg.shared.global [%0], [%1], 16, %2;"
                 :: "r"(dst), "l"(src), "r"(sz) : "memory");
}
#define CP_COMMIT() asm volatile("cp.async.commit_group;" ::: "memory")
#define CP_WAIT(n)  asm volatile("cp.async.wait_group %0;" :: "n"(n) : "memory")

__device__ __forceinline__ void mma16816(float* d,
    uint32_t a0, uint32_t a1, uint32_t a2, uint32_t a3,
    uint32_t b0, uint32_t b1) {
    asm volatile(
        "mma.sync.aligned.m16n8k16.row.col.f32.bf16.bf16.f32 "
        "{%0,%1,%2,%3}, {%4,%5,%6,%7}, {%8,%9}, {%0,%1,%2,%3};"
        : "+f"(d[0]), "+f"(d[1]), "+f"(d[2]), "+f"(d[3])
        : "r"(a0), "r"(a1), "r"(a2), "r"(a3), "r"(b0), "r"(b1));
}

#define SWZ(x)  ((x) ^ (((x) >> 3) & 0x70))   // 128B rows
#define SWZ2(x) ((x) ^ (((x) >> 5) & 0x70))   // 512B rows

__device__ __forceinline__ unsigned short f2bf(float x) {
    unsigned short u; asm("cvt.rn.bf16.f32 %0, %1;" : "=h"(u) : "f"(x)); return u;
}
__device__ __forceinline__ float bf2f(unsigned short u) {
    return __uint_as_float(((uint32_t)u) << 16);
}
__device__ __forceinline__ void split2(float x, unsigned short& h, unsigned short& l) {
    h = f2bf(x);
    l = f2bf(x - bf2f(h));
}

// ---------------- bucketing ----------------
__global__ void k_zero() {
    int t = threadIdx.x;
    if (t < NBn) { g_counts[t] = 0; g_cursor[t] = 0; }
}
__global__ void k_count(const int* __restrict__ cmd) {
    __shared__ int loc[NBn];
    if (threadIdx.x < NBn) loc[threadIdx.x] = 0;
    __syncthreads();
    int i = blockIdx.x * blockDim.x + threadIdx.x;
    if (i < Bn) atomicAdd(&loc[cmd[i] - 1], 1);
    __syncthreads();
    if (threadIdx.x < NBn) atomicAdd(&g_counts[threadIdx.x], loc[threadIdx.x]);
}
__global__ void k_scan() {
    int acc = 0;
    for (int g = 0; g < NBn; g++) {
        g_poff[g] = acc;
        acc += (g_counts[g] + TM - 1) & ~(TM - 1);
    }
    g_poff[NBn] = acc;
}
__global__ void k_scatter(const int* __restrict__ cmd) {
    int i = blockIdx.x * blockDim.x + threadIdx.x;
    if (i < Bn) {
        int g = cmd[i] - 1;
        int idx = atomicAdd(&g_cursor[g], 1);
        g_perm[g_poff[g] + idx] = i;
    }
}

// -------- speed_in piecewise-linear precompute (single CTA) ---------------
// s(speed) = W2^T relu(speed*w1 + b1) + b2 is piecewise-linear in the scalar
// speed with 256 breakpoints t_j = -b1_j/w1_j. Build 257 interval snapshots
// (u_i, v_i) so that s = speed*u_i + v_i inside interval i.
__global__ __launch_bounds__(256) void k_pwprep(
    const float* __restrict__ w1, const float* __restrict__ b1,
    const float* __restrict__ W2, const float* __restrict__ b2)
{
    __shared__ float w1s[256], b1s[256], thr[256];
    __shared__ int sidx[256];
    const float INF = __int_as_float(0x7f800000);
    int t = threadIdx.x;
    float w = w1[t], b = b1[t];
    w1s[t] = w; b1s[t] = b;
    float tv = (w != 0.f) ? (-b / w) : INF;
    thr[t] = tv;
    __syncthreads();
    int r = 0;
    for (int k = 0; k < 256; k++) {
        float tk = thr[k];
        if (tk < tv || (tk == tv && k < t)) r++;
    }
    sidx[r] = t;
    g_thr[r] = tv;
    __syncthreads();
    if (t < 128) {
        int c = t;
        float u = 0.f, v = b2[c];
        // interval 0: speed = -inf  -> active iff w1<0, or w1==0 && b1>0
        for (int j = 0; j < 256; j++) {
            float wj = w1s[j];
            bool act = (wj < 0.f) || (wj == 0.f && b1s[j] > 0.f);
            if (act) {
                float w2 = W2[j * SLn + c];
                u += wj * w2; v += b1s[j] * w2;
            }
        }
        g_pw[c] = u; g_pw[128 + c] = v;
        for (int i = 1; i <= 256; i++) {
            int j = sidx[i - 1];
            float wj = w1s[j];
            if (wj != 0.f) {
                float w2 = W2[j * SLn + c];
                float sg = (wj > 0.f) ? 1.f : -1.f;
                u += sg * wj * w2; v += sg * b1s[j] * w2;
            }
            g_pw[i * 256 + c] = u; g_pw[i * 256 + 128 + c] = v;
        }
    }
}

// -------- convert A rows (emb || speed_in(speed)) -> bf16 hi/lo [B,640] ---
__global__ __launch_bounds__(256) void k_convA(
    const float* __restrict__ emb, const float* __restrict__ speed)
{
    size_t quad = (size_t)blockIdx.x * 256 + threadIdx.x;
    size_t b = quad / 160;
    int d0 = (int)(quad - b * 160) * 4;
    float4 v;
    if (d0 < En) {
        v = *(const float4*)(emb + b * En + d0);
    } else {
        float spd = speed[b];
        int lo = 0, hi = 256;
        while (lo < hi) {
            int mid = (lo + hi) >> 1;
            if (g_thr[mid] < spd) lo = mid + 1; else hi = mid;
        }
        const float* pw = g_pw + (size_t)lo * 256 + (d0 - En);
        v.x = spd * pw[0] + pw[128];
        v.y = spd * pw[1] + pw[129];
        v.z = spd * pw[2] + pw[130];
        v.w = spd * pw[3] + pw[131];
    }
    unsigned short h0, h1, h2, h3, l0, l1, l2, l3;
    split2(v.x, h0, l0); split2(v.y, h1, l1);
    split2(v.z, h2, l2); split2(v.w, h3, l3);
    uint2 H, L;
    H.x = ((uint32_t)h1 << 16) | h0; H.y = ((uint32_t)h3 << 16) | h2;
    L.x = ((uint32_t)l1 << 16) | l0; L.y = ((uint32_t)l3 << 16) | l2;
    *(uint2*)&g_Ahi[b * Dn + d0] = H;
    *(uint2*)&g_Alo[b * Dn + d0] = L;
}

// -------- transpose + convert weights: [Kd,256] -> [7][256][Kd] hi/lo -----
__global__ __launch_bounds__(256) void k_convW(
    const float* __restrict__ srcB, const float* __restrict__ srcS,
    unsigned short* __restrict__ dhi, unsigned short* __restrict__ dlo, int Kd)
{
    __shared__ float tile[32][33];
    int ntk = Kd / 32;
    int bid = blockIdx.x;
    int g = bid / (ntk * 8);
    int rem = bid - g * ntk * 8;
    int kt = rem / 8, nt = rem - (rem / 8) * 8;
    const float* src = (g < 6) ? srcB + (size_t)g * Kd * 256 : srcS;
    int tid = threadIdx.x;
#pragma unroll
    for (int i = 0; i < 4; i++) {
        int idx = i * 256 + tid;
        int kk = idx >> 5, nn = idx & 31;
        tile[kk][nn] = src[(size_t)(kt * 32 + kk) * 256 + nt * 32 + nn];
    }
    __syncthreads();
#pragma unroll
    for (int i = 0; i < 4; i++) {
        int idx = i * 256 + tid;
        int nn = idx >> 5, kk = idx & 31;
        float x = tile[kk][nn];
        unsigned short h, l; split2(x, h, l);
        size_t o = ((size_t)g * 256 + nt * 32 + nn) * Kd + kt * 32 + kk;
        dhi[o] = h; dlo[o] = l;
    }
}

// ---------------- fused MLP via mma.sync (HMMA, base ISA) ----------------
#define S_STG(s) ((uint32_t)(s) * 98304u)
#define S_AHI(s) (S_STG(s))
#define S_ALO(s) (S_STG(s) + 16384u)
#define S_BHI(s) (S_STG(s) + 32768u)
#define S_BLO(s) (S_STG(s) + 65536u)
#define S_A2HI   0u
#define S_A2LO   65536u
#define S_B2HI   131072u
#define S_B2LO   163840u
#define S_BIAS1  196608u
#define S_BIAS2  197632u
#define S_W3     198656u
#define S_B3     201728u
#define S_ROWS   201744u
#define S_SRED   202256u
#define SMEM_TOT 203808

__global__ __launch_bounds__(512, 1) void k_mlp(
    const float* __restrict__ bb1, const float* __restrict__ bb2,
    const float* __restrict__ bW3, const float* __restrict__ bb3,
    const float* __restrict__ so_b1, const float* __restrict__ so_b2,
    const float* __restrict__ so_W3, const float* __restrict__ so_b3,
    float* __restrict__ out)
{
    extern __shared__ unsigned char sm[];
    int tid = threadIdx.x;
    int wid = tid >> 5, lane = tid & 31;
    int wm = wid & 3, wn = wid >> 2;
    int bid = blockIdx.x;
    bool is_speed = (bid < Bn / TM);
    int g, row0;
    if (is_speed) { g = 6; row0 = bid * TM; }
    else {
        int t = bid - Bn / TM;
        row0 = t * TM;
        if (row0 >= g_poff[NBn]) return;
        g = 0;
#pragma unroll
        for (int i = 0; i < NBn - 1; i++) if (row0 >= g_poff[i + 1]) g = i + 1;
    }
    uint32_t sb = smem_u32(sm);
    float* bias1s = (float*)(sm + S_BIAS1);
    float* bias2s = (float*)(sm + S_BIAS2);
    float* w3s    = (float*)(sm + S_W3);
    float* b3s    = (float*)(sm + S_B3);
    int*   rows_s = (int*)(sm + S_ROWS);
    float* sred   = (float*)(sm + S_SRED);

    if (tid < TM) {
        if (is_speed) rows_s[tid] = row0 + tid;
        else {
            int base = g_poff[g], cnt = g_counts[g];
            int l = row0 - base + tid;
            rows_s[tid] = (l < cnt) ? g_perm[base + l] : -1;
        }
    }
    if (tid < Hn) {
        bias1s[tid] = is_speed ? so_b1[tid] : bb1[g * Hn + tid];
        bias2s[tid] = is_speed ? so_b2[tid] : bb2[g * Hn + tid];
    }
    if (is_speed) { if (tid < Hn) w3s[tid] = so_W3[tid]; }
    else { for (int i = tid; i < Hn * 3; i += 512) w3s[i] = bW3[g * Hn * 3 + i]; }
    if (tid < (is_speed ? 1 : 3)) b3s[tid] = is_speed ? so_b3[0] : bb3[g * 3 + tid];
    if (tid < TM * 3) sred[tid] = 0.f;
    __syncthreads();

    auto fill1 = [&](int s, int c) {
#pragma unroll
        for (int it = 0; it < 2; ++it) {
            int idx = it * 512 + tid;
            int r = idx >> 3, seg = idx & 7;
            int orow = rows_s[r];
            size_t go = (orow >= 0) ? ((size_t)orow * Dn + c * 64 + seg * 8) : 0;
            int sz = (orow >= 0) ? 16 : 0;
            uint32_t sw = SWZ((uint32_t)(r * 128 + seg * 16));
            cpa16(sb + S_AHI(s) + sw, g_Ahi + go, sz);
            cpa16(sb + S_ALO(s) + sw, g_Alo + go, sz);
        }
#pragma unroll
        for (int it = 0; it < 4; ++it) {
            int idx = it * 512 + tid;
            int n = idx >> 3, seg = idx & 7;
            size_t go = ((size_t)g * 256 + n) * Dn + c * 64 + seg * 8;
            uint32_t sw = SWZ((uint32_t)(n * 128 + seg * 16));
            cpa16(sb + S_BHI(s) + sw, g_W1hi + go, 16);
            cpa16(sb + S_BLO(s) + sw, g_W1lo + go, 16);
        }
        CP_COMMIT();
    };
    auto fill2 = [&](int c2) {
#pragma unroll
        for (int it = 0; it < 4; ++it) {
            int idx = it * 512 + tid;
            int n = idx >> 3, seg = idx & 7;
            size_t go = ((size_t)g * 256 + n) * Hn + c2 * 64 + seg * 8;
            uint32_t sw = SWZ((uint32_t)(n * 128 + seg * 16));
            cpa16(sb + S_B2HI + sw, g_W2hi + go, 16);
            cpa16(sb + S_B2LO + sw, g_W2lo + go, 16);
        }
        CP_COMMIT();
    };

    float acc[2][8][4];
#pragma unroll
    for (int m = 0; m < 2; m++)
#pragma unroll
        for (int n = 0; n < 8; n++)
#pragma unroll
            for (int j = 0; j < 4; j++) acc[m][n][j] = 0.f;

    // ================= layer 1: 10 chunks of k=64, double-buffered =========
    fill1(0, 0);
    fill1(1, 1);
    for (int c = 0; c < 10; ++c) {
        int s = c & 1;
        if (c < 9) { CP_WAIT(1); } else { CP_WAIT(0); }
        __syncthreads();
        uint32_t aHiB = S_AHI(s), aLoB = S_ALO(s);
        uint32_t bHiB = S_BHI(s), bLoB = S_BLO(s);
#pragma unroll
        for (int ks = 0; ks < 4; ++ks) {
            uint32_t cb = (uint32_t)(ks * 32 + (lane & 3) * 4);
            uint32_t ah[2][4], al[2][4];
#pragma unroll
            for (int m = 0; m < 2; m++) {
                uint32_t r = (uint32_t)(wm * 32 + m * 16 + (lane >> 2));
                uint32_t o0 = SWZ(r * 128 + cb);
                uint32_t o1 = SWZ((r + 8) * 128 + cb);
                uint32_t o2 = SWZ(r * 128 + cb + 16);
                uint32_t o3 = SWZ((r + 8) * 128 + cb + 16);
                ah[m][0] = *(uint32_t*)(sm + aHiB + o0);
                ah[m][1] = *(uint32_t*)(sm + aHiB + o1);
                ah[m][2] = *(uint32_t*)(sm + aHiB + o2);
                ah[m][3] = *(uint32_t*)(sm + aHiB + o3);
                al[m][0] = *(uint32_t*)(sm + aLoB + o0);
                al[m][1] = *(uint32_t*)(sm + aLoB + o1);
                al[m][2] = *(uint32_t*)(sm + aLoB + o2);
                al[m][3] = *(uint32_t*)(sm + aLoB + o3);
            }
#pragma unroll
            for (int nt = 0; nt < 8; ++nt) {
                uint32_t n = (uint32_t)(wn * 64 + nt * 8 + (lane >> 2));
                uint32_t p0 = SWZ(n * 128 + cb), p1 = SWZ(n * 128 + cb + 16);
                uint32_t bh0 = *(uint32_t*)(sm + bHiB + p0);
                uint32_t bh1 = *(uint32_t*)(sm + bHiB + p1);
                uint32_t bl0 = *(uint32_t*)(sm + bLoB + p0);
                uint32_t bl1 = *(uint32_t*)(sm + bLoB + p1);
#pragma unroll
                for (int m = 0; m < 2; m++) {
                    mma16816(acc[m][nt], ah[m][0], ah[m][1], ah[m][2], ah[m][3], bh0, bh1);
                    mma16816(acc[m][nt], ah[m][0], ah[m][1], ah[m][2], ah[m][3], bl0, bl1);
                    mma16816(acc[m][nt], al[m][0], al[m][1], al[m][2], al[m][3], bh0, bh1);
                }
            }
        }
        __syncthreads();
        if (c + 2 < 10) fill1(s, c + 2);
    }

    fill2(0);

    // ===== epilogue 1: relu(D+b1) -> bf16 hi/lo into A2 (512B rows, SWZ2) ==
#pragma unroll
    for (int m = 0; m < 2; m++) {
#pragma unroll
        for (int half = 0; half < 2; half++) {
            uint32_t r = (uint32_t)(wm * 32 + m * 16 + half * 8 + (lane >> 2));
#pragma unroll
            for (int nt = 0; nt < 8; ++nt) {
                int c0 = wn * 64 + nt * 8 + (lane & 3) * 2;
                float v0 = acc[m][nt][half * 2 + 0] + bias1s[c0];
                float v1 = acc[m][nt][half * 2 + 1] + bias1s[c0 + 1];
                v0 = fmaxf(v0, 0.f); v1 = fmaxf(v1, 0.f);
                unsigned short h0, h1, l0, l1;
                split2(v0, h0, l0); split2(v1, h1, l1);
                uint32_t byte = SWZ2((uint32_t)(r * 512 + c0 * 2));
                *(uint32_t*)(sm + S_A2HI + byte) = ((uint32_t)h1 << 16) | h0;
                *(uint32_t*)(sm + S_A2LO + byte) = ((uint32_t)l1 << 16) | l0;
            }
        }
    }
#pragma unroll
    for (int m = 0; m < 2; m++)
#pragma unroll
        for (int n = 0; n < 8; n++)
#pragma unroll
            for (int j = 0; j < 4; j++) acc[m][n][j] = 0.f;

    // ================= layer 2: 4 chunks of k=64 ===========================
    for (int c2 = 0; c2 < 4; ++c2) {
        CP_WAIT(0);
        __syncthreads();
#pragma unroll
        for (int ks = 0; ks < 4; ++ks) {
            uint32_t kg = (uint32_t)(c2 * 64 + ks * 16 + (lane & 3) * 2) * 2;
            uint32_t cb = (uint32_t)(ks * 32 + (lane & 3) * 4);
            uint32_t ah[2][4], al[2][4];
#pragma unroll
            for (int m = 0; m < 2; m++) {
                uint32_t r = (uint32_t)(wm * 32 + m * 16 + (lane >> 2));
                uint32_t o0 = SWZ2(r * 512 + kg);
                uint32_t o1 = SWZ2((r + 8) * 512 + kg);
                uint32_t o2 = SWZ2(r * 512 + kg + 16);
                uint32_t o3 = SWZ2((r + 8) * 512 + kg + 16);
                ah[m][0] = *(uint32_t*)(sm + S_A2HI + o0);
                ah[m][1] = *(uint32_t*)(sm + S_A2HI + o1);
                ah[m][2] = *(uint32_t*)(sm + S_A2HI + o2);
                ah[m][3] = *(uint32_t*)(sm + S_A2HI + o3);
                al[m][0] = *(uint32_t*)(sm + S_A2LO + o0);
                al[m][1] = *(uint32_t*)(sm + S_A2LO + o1);
                al[m][2] = *(uint32_t*)(sm + S_A2LO + o2);
                al[m][3] = *(uint32_t*)(sm + S_A2LO + o3);
            }
#pragma unroll
            for (int nt = 0; nt < 8; ++nt) {
                uint32_t n = (uint32_t)(wn * 64 + nt * 8 + (lane >> 2));
                uint32_t p0 = SWZ(n * 128 + cb), p1 = SWZ(n * 128 + cb + 16);
                uint32_t bh0 = *(uint32_t*)(sm + S_B2HI + p0);
                uint32_t bh1 = *(uint32_t*)(sm + S_B2HI + p1);
                uint32_t bl0 = *(uint32_t*)(sm + S_B2LO + p0);
                uint32_t bl1 = *(uint32_t*)(sm + S_B2LO + p1);
#pragma unroll
                for (int m = 0; m < 2; m++) {
                    mma16816(acc[m][nt], ah[m][0], ah[m][1], ah[m][2], ah[m][3], bh0, bh1);
                    mma16816(acc[m][nt], ah[m][0], ah[m][1], ah[m][2], ah[m][3], bl0, bl1);
                    mma16816(acc[m][nt], al[m][0], al[m][1], al[m][2], al[m][3], bh0, bh1);
                }
            }
        }
        __syncthreads();
        if (c2 + 1 < 4) fill2(c2 + 1);
    }

    // ===== epilogue 2: relu(D+b2), layer-3 dot, reduce, activate, scatter ==
#pragma unroll
    for (int m = 0; m < 2; m++) {
#pragma unroll
        for (int half = 0; half < 2; half++) {
            int rl = wm * 32 + m * 16 + half * 8 + (lane >> 2);
            float p0 = 0.f, p1 = 0.f, p2 = 0.f;
#pragma unroll
            for (int nt = 0; nt < 8; ++nt) {
                int c0 = wn * 64 + nt * 8 + (lane & 3) * 2;
                float v0 = fmaxf(acc[m][nt][half * 2 + 0] + bias2s[c0], 0.f);
                float v1 = fmaxf(acc[m][nt][half * 2 + 1] + bias2s[c0 + 1], 0.f);
                if (is_speed) {
                    p0 += v0 * w3s[c0] + v1 * w3s[c0 + 1];
                } else {
                    p0 += v0 * w3s[c0 * 3]     + v1 * w3s[(c0 + 1) * 3];
                    p1 += v0 * w3s[c0 * 3 + 1] + v1 * w3s[(c0 + 1) * 3 + 1];
                    p2 += v0 * w3s[c0 * 3 + 2] + v1 * w3s[(c0 + 1) * 3 + 2];
                }
            }
#pragma unroll
            for (int d = 1; d < 4; d <<= 1) {
                p0 += __shfl_xor_sync(0xffffffffu, p0, d);
                p1 += __shfl_xor_sync(0xffffffffu, p1, d);
                p2 += __shfl_xor_sync(0xffffffffu, p2, d);
            }
            if ((lane & 3) == 0) {
                if (is_speed) atomicAdd(&sred[rl], p0);
                else {
                    atomicAdd(&sred[rl * 3 + 0], p0);
                    atomicAdd(&sred[rl * 3 + 1], p1);
                    atomicAdd(&sred[rl * 3 + 2], p2);
                }
            }
        }
    }
    __syncthreads();
    if (tid < TM) {
        int orow = rows_s[tid];
        if (is_speed) {
            out[(size_t)Bn * 3 + orow] = sred[tid] + b3s[0];
        } else if (orow >= 0) {
            float s0 = sred[tid * 3 + 0] + b3s[0];
            float s1 = sred[tid * 3 + 1] + b3s[1];
            float s2 = sred[tid * 3 + 2] + b3s[2];
            out[(size_t)orow * 3 + 0] = 1.f / (1.f + expf(-s0));
            out[(size_t)orow * 3 + 1] = 1.f / (1.f + expf(-s1));
            out[(size_t)orow * 3 + 2] = 1.f / (1.f + expf(-s2));
        }
    }
}

// ---------------- launcher ----------------
extern "C" void kernel_launch(void* const* d_in, const int* in_sizes, int n_in,
                              void* d_out, int out_size) {
    const float* embedding = (const float*)d_in[0];
    const float* speed     = (const float*)d_in[1];
    const int*   command   = (const int*)d_in[2];
    const float* si_W1 = (const float*)d_in[3];
    const float* si_b1 = (const float*)d_in[4];
    const float* si_W2 = (const float*)d_in[5];
    const float* si_b2 = (const float*)d_in[6];
    const float* bW1   = (const float*)d_in[7];
    const float* bb1   = (const float*)d_in[8];
    const float* bW2   = (const float*)d_in[9];
    const float* bb2   = (const float*)d_in[10];
    const float* bW3   = (const float*)d_in[11];
    const float* bb3   = (const float*)d_in[12];
    const float* so_W1 = (const float*)d_in[13];
    const float* so_b1 = (const float*)d_in[14];
    const float* so_W2 = (const float*)d_in[15];
    const float* so_b2 = (const float*)d_in[16];
    const float* so_W3 = (const float*)d_in[17];
    const float* so_b3 = (const float*)d_in[18];
    float* out = (float*)d_out;

    unsigned short *w1hi, *w1lo, *w2hi, *w2lo;
    cudaGetSymbolAddress((void**)&w1hi, g_W1hi);
    cudaGetSymbolAddress((void**)&w1lo, g_W1lo);
    cudaGetSymbolAddress((void**)&w2hi, g_W2hi);
    cudaGetSymbolAddress((void**)&w2lo, g_W2lo);

    cudaFuncSetAttribute(k_mlp, cudaFuncAttributeMaxDynamicSharedMemorySize, SMEM_TOT);

    k_zero<<<1, 32>>>();
    k_count<<<Bn / 256, 256>>>(command);
    k_scan<<<1, 1>>>();
    k_scatter<<<Bn / 256, 256>>>(command);
    k_pwprep<<<1, 256>>>(si_W1, si_b1, si_W2, si_b2);
    k_convA<<<(int)(((size_t)Bn * Dn / 4) / 256), 256>>>(embedding, speed);
    k_convW<<<7 * (Dn / 32) * 8, 256>>>(bW1, so_W1, w1hi, w1lo, Dn);
    k_convW<<<7 * (Hn / 32) * 8, 256>>>(bW2, so_W2, w2hi, w2lo, Hn);

    int branch_tiles = (Bn + NBn * (TM - 1)) / TM + 1;   // 518
    k_mlp<<<Bn / TM + branch_tiles, 512, SMEM_TOT>>>(
        bb1, bb2, bW3, bb3, so_b1, so_b2, so_W3, so_b3, out);
}

// round 9
// speedup vs baseline: 5.7607x; 1.2465x over previous
#include <cuda_runtime.h>
#include <cuda_fp16.h>
#include <math.h>
#include <stdint.h>

#define Bn  65536
#define En  512
#define SLn 128
#define Hn  256
#define NBn 6
#define Dn  640
#define TM  128

// ---------------- scratch (static device globals; no allocations) ---------
__device__ int   g_perm[Bn + NBn * TM];
__device__ int   g_counts[NBn];
__device__ int   g_cursor[NBn];
__device__ int   g_poff[NBn + 1];
__device__ float g_thr[256];             // sorted relu breakpoints of speed_in
__device__ float g_pw[257 * 256];        // per-interval [u(128) | v(128)]
__device__ __align__(16) unsigned short g_A[(size_t)Bn * Dn];      // fp16
__device__ __align__(16) unsigned short g_W1hi[7 * 256 * Dn];      // fp16
__device__ __align__(16) unsigned short g_W1lo[7 * 256 * Dn];
__device__ __align__(16) unsigned short g_W2hi[7 * 256 * Hn];
__device__ __align__(16) unsigned short g_W2lo[7 * 256 * Hn];

// ---------------- helpers ----------------
__device__ __forceinline__ uint32_t smem_u32(const void* p) {
    uint32_t a;
    asm("{ .reg .u64 t; cvta.to.shared.u64 t, %1; cvt.u32.u64 %0, t; }" : "=r"(a) : "l"(p));
    return a;
}
__device__ __forceinline__ void cpa16(uint32_t dst, const void* src, int sz) {
    asm volatile("cp.async.cg.shared.global [%0], [%1], 16, %2;"
                 :: "r"(dst), "l"(src), "r"(sz) : "memory");
}
#define CP_COMMIT() asm volatile("cp.async.commit_group;" ::: "memory")
#define CP_WAIT(n)  asm volatile("cp.async.wait_group %0;" :: "n"(n) : "memory")

__device__ __forceinline__ void mma_h(float* d,
    uint32_t a0, uint32_t a1, uint32_t a2, uint32_t a3,
    uint32_t b0, uint32_t b1) {
    asm volatile(
        "mma.sync.aligned.m16n8k16.row.col.f32.f16.f16.f32 "
        "{%0,%1,%2,%3}, {%4,%5,%6,%7}, {%8,%9}, {%0,%1,%2,%3};"
        : "+f"(d[0]), "+f"(d[1]), "+f"(d[2]), "+f"(d[3])
        : "r"(a0), "r"(a1), "r"(a2), "r"(a3), "r"(b0), "r"(b1));
}

#define SWZ(x)  ((x) ^ (((x) >> 3) & 0x70))   // 128B rows
#define SWZ2(x) ((x) ^ (((x) >> 5) & 0x70))   // 512B rows

__device__ __forceinline__ unsigned short f2h(float x) {
    unsigned short u; asm("cvt.rn.f16.f32 %0, %1;" : "=h"(u) : "f"(x)); return u;
}
__device__ __forceinline__ float h2f(unsigned short u) {
    float f; asm("cvt.f32.f16 %0, %1;" : "=f"(f) : "h"(u)); return f;
}
__device__ __forceinline__ void split2h(float x, unsigned short& h, unsigned short& l) {
    h = f2h(x);
    l = f2h(x - h2f(h));
}

// ---------------- bucketing ----------------
__global__ void k_zero() {
    int t = threadIdx.x;
    if (t < NBn) { g_counts[t] = 0; g_cursor[t] = 0; }
}
__global__ void k_count(const int* __restrict__ cmd) {
    __shared__ int loc[NBn];
    if (threadIdx.x < NBn) loc[threadIdx.x] = 0;
    __syncthreads();
    int i = blockIdx.x * blockDim.x + threadIdx.x;
    if (i < Bn) atomicAdd(&loc[cmd[i] - 1], 1);
    __syncthreads();
    if (threadIdx.x < NBn) atomicAdd(&g_counts[threadIdx.x], loc[threadIdx.x]);
}
__global__ void k_scan() {
    int acc = 0;
    for (int g = 0; g < NBn; g++) {
        g_poff[g] = acc;
        acc += (g_counts[g] + TM - 1) & ~(TM - 1);
    }
    g_poff[NBn] = acc;
}
__global__ void k_scatter(const int* __restrict__ cmd) {
    int i = blockIdx.x * blockDim.x + threadIdx.x;
    if (i < Bn) {
        int g = cmd[i] - 1;
        int idx = atomicAdd(&g_cursor[g], 1);
        g_perm[g_poff[g] + idx] = i;
    }
}

// -------- speed_in piecewise-linear precompute (single CTA) ---------------
__global__ __launch_bounds__(256) void k_pwprep(
    const float* __restrict__ w1, const float* __restrict__ b1,
    const float* __restrict__ W2, const float* __restrict__ b2)
{
    __shared__ float w1s[256], b1s[256], thr[256];
    __shared__ int sidx[256];
    const float INF = __int_as_float(0x7f800000);
    int t = threadIdx.x;
    float w = w1[t], b = b1[t];
    w1s[t] = w; b1s[t] = b;
    float tv = (w != 0.f) ? (-b / w) : INF;
    thr[t] = tv;
    __syncthreads();
    int r = 0;
    for (int k = 0; k < 256; k++) {
        float tk = thr[k];
        if (tk < tv || (tk == tv && k < t)) r++;
    }
    sidx[r] = t;
    g_thr[r] = tv;
    __syncthreads();
    if (t < 128) {
        int c = t;
        float u = 0.f, v = b2[c];
        for (int j = 0; j < 256; j++) {
            float wj = w1s[j];
            bool act = (wj < 0.f) || (wj == 0.f && b1s[j] > 0.f);
            if (act) {
                float w2 = W2[j * SLn + c];
                u += wj * w2; v += b1s[j] * w2;
            }
        }
        g_pw[c] = u; g_pw[128 + c] = v;
        for (int i = 1; i <= 256; i++) {
            int j = sidx[i - 1];
            float wj = w1s[j];
            if (wj != 0.f) {
                float w2 = W2[j * SLn + c];
                float sg = (wj > 0.f) ? 1.f : -1.f;
                u += sg * wj * w2; v += sg * b1s[j] * w2;
            }
            g_pw[i * 256 + c] = u; g_pw[i * 256 + 128 + c] = v;
        }
    }
}

// -------- convert A rows (emb || speed_in(speed)) -> fp16 [B,640] ---------
__global__ __launch_bounds__(256) void k_convA(
    const float* __restrict__ emb, const float* __restrict__ speed)
{
    size_t quad = (size_t)blockIdx.x * 256 + threadIdx.x;
    size_t b = quad / 160;
    int d0 = (int)(quad - b * 160) * 4;
    float4 v;
    if (d0 < En) {
        v = *(const float4*)(emb + b * En + d0);
    } else {
        float spd = speed[b];
        int lo = 0, hi = 256;
        while (lo < hi) {
            int mid = (lo + hi) >> 1;
            if (g_thr[mid] < spd) lo = mid + 1; else hi = mid;
        }
        const float* pw = g_pw + (size_t)lo * 256 + (d0 - En);
        v.x = spd * pw[0] + pw[128];
        v.y = spd * pw[1] + pw[129];
        v.z = spd * pw[2] + pw[130];
        v.w = spd * pw[3] + pw[131];
    }
    uint2 H;
    H.x = ((uint32_t)f2h(v.y) << 16) | f2h(v.x);
    H.y = ((uint32_t)f2h(v.w) << 16) | f2h(v.z);
    *(uint2*)&g_A[b * Dn + d0] = H;
}

// -------- transpose + convert weights: [Kd,256] -> [7][256][Kd] hi/lo -----
__global__ __launch_bounds__(256) void k_convW(
    const float* __restrict__ srcB, const float* __restrict__ srcS,
    unsigned short* __restrict__ dhi, unsigned short* __restrict__ dlo, int Kd)
{
    __shared__ float tile[32][33];
    int ntk = Kd / 32;
    int bid = blockIdx.x;
    int g = bid / (ntk * 8);
    int rem = bid - g * ntk * 8;
    int kt = rem / 8, nt = rem - (rem / 8) * 8;
    const float* src = (g < 6) ? srcB + (size_t)g * Kd * 256 : srcS;
    int tid = threadIdx.x;
#pragma unroll
    for (int i = 0; i < 4; i++) {
        int idx = i * 256 + tid;
        int kk = idx >> 5, nn = idx & 31;
        tile[kk][nn] = src[(size_t)(kt * 32 + kk) * 256 + nt * 32 + nn];
    }
    __syncthreads();
#pragma unroll
    for (int i = 0; i < 4; i++) {
        int idx = i * 256 + tid;
        int nn = idx >> 5, kk = idx & 31;
        float x = tile[kk][nn];
        unsigned short h, l; split2h(x, h, l);
        size_t o = ((size_t)g * 256 + nt * 32 + nn) * Kd + kt * 32 + kk;
        dhi[o] = h; dlo[o] = l;
    }
}

// ---------------- fused MLP via mma.sync (fp16 HMMA, 2-term) --------------
#define S_STG(s)  ((uint32_t)(s) * 81920u)
#define S_AHI(s)  (S_STG(s))
#define S_BHI(s)  (S_STG(s) + 16384u)
#define S_BLO(s)  (S_STG(s) + 49152u)
#define S_A2      0u
#define S_B2HI(s) (65536u + (uint32_t)(s) * 65536u)
#define S_B2LO(s) (S_B2HI(s) + 32768u)
#define S_BIAS1  196608u
#define S_BIAS2  197632u
#define S_W3     198656u
#define S_B3     201728u
#define S_ROWS   201744u
#define S_SRED   202256u
#define SMEM_TOT 203808

__global__ __launch_bounds__(512, 1) void k_mlp(
    const float* __restrict__ bb1, const float* __restrict__ bb2,
    const float* __restrict__ bW3, const float* __restrict__ bb3,
    const float* __restrict__ so_b1, const float* __restrict__ so_b2,
    const float* __restrict__ so_W3, const float* __restrict__ so_b3,
    float* __restrict__ out)
{
    extern __shared__ unsigned char sm[];
    int tid = threadIdx.x;
    int wid = tid >> 5, lane = tid & 31;
    int wm = wid & 3, wn = wid >> 2;
    int bid = blockIdx.x;
    bool is_speed = (bid < Bn / TM);
    int g, row0;
    if (is_speed) { g = 6; row0 = bid * TM; }
    else {
        int t = bid - Bn / TM;
        row0 = t * TM;
        if (row0 >= g_poff[NBn]) return;
        g = 0;
#pragma unroll
        for (int i = 0; i < NBn - 1; i++) if (row0 >= g_poff[i + 1]) g = i + 1;
    }
    uint32_t sb = smem_u32(sm);
    float* bias1s = (float*)(sm + S_BIAS1);
    float* bias2s = (float*)(sm + S_BIAS2);
    float* w3s    = (float*)(sm + S_W3);
    float* b3s    = (float*)(sm + S_B3);
    int*   rows_s = (int*)(sm + S_ROWS);
    float* sred   = (float*)(sm + S_SRED);

    if (tid < TM) {
        if (is_speed) rows_s[tid] = row0 + tid;
        else {
            int base = g_poff[g], cnt = g_counts[g];
            int l = row0 - base + tid;
            rows_s[tid] = (l < cnt) ? g_perm[base + l] : -1;
        }
    }
    if (tid < Hn) {
        bias1s[tid] = is_speed ? so_b1[tid] : bb1[g * Hn + tid];
        bias2s[tid] = is_speed ? so_b2[tid] : bb2[g * Hn + tid];
    }
    if (is_speed) { if (tid < Hn) w3s[tid] = so_W3[tid]; }
    else { for (int i = tid; i < Hn * 3; i += 512) w3s[i] = bW3[g * Hn * 3 + i]; }
    if (tid < (is_speed ? 1 : 3)) b3s[tid] = is_speed ? so_b3[0] : bb3[g * 3 + tid];
    if (tid < TM * 3) sred[tid] = 0.f;
    __syncthreads();

    auto fill1 = [&](int s, int c) {
        // A fp16 single: 128 rows x 8 x 16B
#pragma unroll
        for (int it = 0; it < 2; ++it) {
            int idx = it * 512 + tid;
            int r = idx >> 3, seg = idx & 7;
            int orow = rows_s[r];
            size_t go = (orow >= 0) ? ((size_t)orow * Dn + c * 64 + seg * 8) : 0;
            int sz = (orow >= 0) ? 16 : 0;
            uint32_t sw = SWZ((uint32_t)(r * 128 + seg * 16));
            cpa16(sb + S_AHI(s) + sw, g_A + go, sz);
        }
        // B hi/lo: 256 rows x 8 x 16B each
#pragma unroll
        for (int it = 0; it < 4; ++it) {
            int idx = it * 512 + tid;
            int n = idx >> 3, seg = idx & 7;
            size_t go = ((size_t)g * 256 + n) * Dn + c * 64 + seg * 8;
            uint32_t sw = SWZ((uint32_t)(n * 128 + seg * 16));
            cpa16(sb + S_BHI(s) + sw, g_W1hi + go, 16);
            cpa16(sb + S_BLO(s) + sw, g_W1lo + go, 16);
        }
        CP_COMMIT();
    };
    auto fill2 = [&](int c2) {
        int s2 = c2 & 1;
#pragma unroll
        for (int it = 0; it < 4; ++it) {
            int idx = it * 512 + tid;
            int n = idx >> 3, seg = idx & 7;
            size_t go = ((size_t)g * 256 + n) * Hn + c2 * 64 + seg * 8;
            uint32_t sw = SWZ((uint32_t)(n * 128 + seg * 16));
            cpa16(sb + S_B2HI(s2) + sw, g_W2hi + go, 16);
            cpa16(sb + S_B2LO(s2) + sw, g_W2lo + go, 16);
        }
        CP_COMMIT();
    };

    float acc[2][8][4];
#pragma unroll
    for (int m = 0; m < 2; m++)
#pragma unroll
        for (int n = 0; n < 8; n++)
#pragma unroll
            for (int j = 0; j < 4; j++) acc[m][n][j] = 0.f;

    // ================= layer 1: 10 chunks of k=64, double-buffered =========
    fill1(0, 0);
    fill1(1, 1);
    for (int c = 0; c < 10; ++c) {
        int s = c & 1;
        if (c < 9) { CP_WAIT(1); } else { CP_WAIT(0); }
        __syncthreads();
        uint32_t aB = S_AHI(s);
        uint32_t bHiB = S_BHI(s), bLoB = S_BLO(s);
#pragma unroll
        for (int ks = 0; ks < 4; ++ks) {
            uint32_t cb = (uint32_t)(ks * 32 + (lane & 3) * 4);
            uint32_t ah[2][4];
#pragma unroll
            for (int m = 0; m < 2; m++) {
                uint32_t r = (uint32_t)(wm * 32 + m * 16 + (lane >> 2));
                ah[m][0] = *(uint32_t*)(sm + aB + SWZ(r * 128 + cb));
                ah[m][1] = *(uint32_t*)(sm + aB + SWZ((r + 8) * 128 + cb));
                ah[m][2] = *(uint32_t*)(sm + aB + SWZ(r * 128 + cb + 16));
                ah[m][3] = *(uint32_t*)(sm + aB + SWZ((r + 8) * 128 + cb + 16));
            }
#pragma unroll
            for (int nt = 0; nt < 8; ++nt) {
                uint32_t n = (uint32_t)(wn * 64 + nt * 8 + (lane >> 2));
                uint32_t p0 = SWZ(n * 128 + cb), p1 = SWZ(n * 128 + cb + 16);
                uint32_t bh0 = *(uint32_t*)(sm + bHiB + p0);
                uint32_t bh1 = *(uint32_t*)(sm + bHiB + p1);
                uint32_t bl0 = *(uint32_t*)(sm + bLoB + p0);
                uint32_t bl1 = *(uint32_t*)(sm + bLoB + p1);
#pragma unroll
                for (int m = 0; m < 2; m++) {
                    mma_h(acc[m][nt], ah[m][0], ah[m][1], ah[m][2], ah[m][3], bh0, bh1);
                    mma_h(acc[m][nt], ah[m][0], ah[m][1], ah[m][2], ah[m][3], bl0, bl1);
                }
            }
        }
        __syncthreads();
        if (c + 2 < 10) fill1(s, c + 2);
    }

    // prefetch both layer-2 weight stages (regions free after final sync)
    fill2(0);
    fill2(1);

    // ===== epilogue 1: relu(D+b1) -> fp16 into A2 (512B rows, SWZ2) ========
#pragma unroll
    for (int m = 0; m < 2; m++) {
#pragma unroll
        for (int half = 0; half < 2; half++) {
            uint32_t r = (uint32_t)(wm * 32 + m * 16 + half * 8 + (lane >> 2));
#pragma unroll
            for (int nt = 0; nt < 8; ++nt) {
                int c0 = wn * 64 + nt * 8 + (lane & 3) * 2;
                float v0 = fmaxf(acc[m][nt][half * 2 + 0] + bias1s[c0], 0.f);
                float v1 = fmaxf(acc[m][nt][half * 2 + 1] + bias1s[c0 + 1], 0.f);
                uint32_t byte = SWZ2((uint32_t)(r * 512 + c0 * 2));
                *(uint32_t*)(sm + S_A2 + byte) = ((uint32_t)f2h(v1) << 16) | f2h(v0);
            }
        }
    }
#pragma unroll
    for (int m = 0; m < 2; m++)
#pragma unroll
        for (int n = 0; n < 8; n++)
#pragma unroll
            for (int j = 0; j < 4; j++) acc[m][n][j] = 0.f;

    // ================= layer 2: 4 chunks of k=64, double-buffered ==========
    for (int c2 = 0; c2 < 4; ++c2) {
        int s2 = c2 & 1;
        if (c2 < 3) { CP_WAIT(1); } else { CP_WAIT(0); }
        __syncthreads();
#pragma unroll
        for (int ks = 0; ks < 4; ++ks) {
            uint32_t kg = (uint32_t)(c2 * 64 + ks * 16 + (lane & 3) * 2) * 2;
            uint32_t cb = (uint32_t)(ks * 32 + (lane & 3) * 4);
            uint32_t ah[2][4];
#pragma unroll
            for (int m = 0; m < 2; m++) {
                uint32_t r = (uint32_t)(wm * 32 + m * 16 + (lane >> 2));
                ah[m][0] = *(uint32_t*)(sm + S_A2 + SWZ2(r * 512 + kg));
                ah[m][1] = *(uint32_t*)(sm + S_A2 + SWZ2((r + 8) * 512 + kg));
                ah[m][2] = *(uint32_t*)(sm + S_A2 + SWZ2(r * 512 + kg + 16));
                ah[m][3] = *(uint32_t*)(sm + S_A2 + SWZ2((r + 8) * 512 + kg + 16));
            }
#pragma unroll
            for (int nt = 0; nt < 8; ++nt) {
                uint32_t n = (uint32_t)(wn * 64 + nt * 8 + (lane >> 2));
                uint32_t p0 = SWZ(n * 128 + cb), p1 = SWZ(n * 128 + cb + 16);
                uint32_t bh0 = *(uint32_t*)(sm + S_B2HI(s2) + p0);
                uint32_t bh1 = *(uint32_t*)(sm + S_B2HI(s2) + p1);
                uint32_t bl0 = *(uint32_t*)(sm + S_B2LO(s2) + p0);
                uint32_t bl1 = *(uint32_t*)(sm + S_B2LO(s2) + p1);
#pragma unroll
                for (int m = 0; m < 2; m++) {
                    mma_h(acc[m][nt], ah[m][0], ah[m][1], ah[m][2], ah[m][3], bh0, bh1);
                    mma_h(acc[m][nt], ah[m][0], ah[m][1], ah[m][2], ah[m][3], bl0, bl1);
                }
            }
        }
        __syncthreads();
        if (c2 + 2 < 4) fill2(c2 + 2);
    }

    // ===== epilogue 2: relu(D+b2), layer-3 dot, reduce, activate, scatter ==
#pragma unroll
    for (int m = 0; m < 2; m++) {
#pragma unroll
        for (int half = 0; half < 2; half++) {
            int rl = wm * 32 + m * 16 + half * 8 + (lane >> 2);
            float p0 = 0.f, p1 = 0.f, p2 = 0.f;
#pragma unroll
            for (int nt = 0; nt < 8; ++nt) {
                int c0 = wn * 64 + nt * 8 + (lane & 3) * 2;
                float v0 = fmaxf(acc[m][nt][half * 2 + 0] + bias2s[c0], 0.f);
                float v1 = fmaxf(acc[m][nt][half * 2 + 1] + bias2s[c0 + 1], 0.f);
                if (is_speed) {
                    p0 += v0 * w3s[c0] + v1 * w3s[c0 + 1];
                } else {
                    p0 += v0 * w3s[c0 * 3]     + v1 * w3s[(c0 + 1) * 3];
                    p1 += v0 * w3s[c0 * 3 + 1] + v1 * w3s[(c0 + 1) * 3 + 1];
                    p2 += v0 * w3s[c0 * 3 + 2] + v1 * w3s[(c0 + 1) * 3 + 2];
                }
            }
#pragma unroll
            for (int d = 1; d < 4; d <<= 1) {
                p0 += __shfl_xor_sync(0xffffffffu, p0, d);
                p1 += __shfl_xor_sync(0xffffffffu, p1, d);
                p2 += __shfl_xor_sync(0xffffffffu, p2, d);
            }
            if ((lane & 3) == 0) {
                if (is_speed) atomicAdd(&sred[rl], p0);
                else {
                    atomicAdd(&sred[rl * 3 + 0], p0);
                    atomicAdd(&sred[rl * 3 + 1], p1);
                    atomicAdd(&sred[rl * 3 + 2], p2);
                }
            }
        }
    }
    __syncthreads();
    if (tid < TM) {
        int orow = rows_s[tid];
        if (is_speed) {
            out[(size_t)Bn * 3 + orow] = sred[tid] + b3s[0];
        } else if (orow >= 0) {
            float s0 = sred[tid * 3 + 0] + b3s[0];
            float s1 = sred[tid * 3 + 1] + b3s[1];
            float s2 = sred[tid * 3 + 2] + b3s[2];
            out[(size_t)orow * 3 + 0] = 1.f / (1.f + expf(-s0));
            out[(size_t)orow * 3 + 1] = 1.f / (1.f + expf(-s1));
            out[(size_t)orow * 3 + 2] = 1.f / (1.f + expf(-s2));
        }
    }
}

// ---------------- launcher ----------------
extern "C" void kernel_launch(void* const* d_in, const int* in_sizes, int n_in,
                              void* d_out, int out_size) {
    const float* embedding = (const float*)d_in[0];
    const float* speed     = (const float*)d_in[1];
    const int*   command   = (const int*)d_in[2];
    const float* si_W1 = (const float*)d_in[3];
    const float* si_b1 = (const float*)d_in[4];
    const float* si_W2 = (const float*)d_in[5];
    const float* si_b2 = (const float*)d_in[6];
    const float* bW1   = (const float*)d_in[7];
    const float* bb1   = (const float*)d_in[8];
    const float* bW2   = (const float*)d_in[9];
    const float* bb2   = (const float*)d_in[10];
    const float* bW3   = (const float*)d_in[11];
    const float* bb3   = (const float*)d_in[12];
    const float* so_W1 = (const float*)d_in[13];
    const float* so_b1 = (const float*)d_in[14];
    const float* so_W2 = (const float*)d_in[15];
    const float* so_b2 = (const float*)d_in[16];
    const float* so_W3 = (const float*)d_in[17];
    const float* so_b3 = (const float*)d_in[18];
    float* out = (float*)d_out;

    unsigned short *w1hi, *w1lo, *w2hi, *w2lo;
    cudaGetSymbolAddress((void**)&w1hi, g_W1hi);
    cudaGetSymbolAddress((void**)&w1lo, g_W1lo);
    cudaGetSymbolAddress((void**)&w2hi, g_W2hi);
    cudaGetSymbolAddress((void**)&w2lo, g_W2lo);

    cudaFuncSetAttribute(k_mlp, cudaFuncAttributeMaxDynamicSharedMemorySize, SMEM_TOT);

    k_zero<<<1, 32>>>();
    k_count<<<Bn / 256, 256>>>(command);
    k_scan<<<1, 1>>>();
    k_scatter<<<Bn / 256, 256>>>(command);
    k_pwprep<<<1, 256>>>(si_W1, si_b1, si_W2, si_b2);
    k_convA<<<(int)(((size_t)Bn * Dn / 4) / 256), 256>>>(embedding, speed);
    k_convW<<<7 * (Dn / 32) * 8, 256>>>(bW1, so_W1, w1hi, w1lo, Dn);
    k_convW<<<7 * (Hn / 32) * 8, 256>>>(bW2, so_W2, w2hi, w2lo, Hn);

    int branch_tiles = (Bn + NBn * (TM - 1)) / TM + 1;   // 518
    k_mlp<<<Bn / TM + branch_tiles, 512, SMEM_TOT>>>(
        bb1, bb2, bW3, bb3, so_b1, so_b2, so_W3, so_b3, out);
}

// round 12
// speedup vs baseline: 7.3261x; 1.2717x over previous
#include <cuda_runtime.h>
#include <cuda_fp16.h>
#include <math.h>
#include <stdint.h>

#define Bn  65536
#define En  512
#define SLn 128
#define Hn  256
#define NBn 6
#define Dn  640
#define TM  128

// ---------------- scratch (static device globals; no allocations) ---------
__device__ int   g_perm[Bn + NBn * TM];
__device__ int   g_counts[NBn];
__device__ int   g_cursor[NBn];
__device__ int   g_poff[NBn + 1];
__device__ float g_thr[256];             // sorted relu breakpoints of speed_in
__device__ float g_pw[257 * 256];        // per-interval [u(128) | v(128)]
__device__ __align__(16) unsigned short g_A[(size_t)Bn * Dn];      // fp16
__device__ __align__(16) unsigned short g_W1[7 * 256 * Dn];        // fp16
__device__ __align__(16) unsigned short g_W2[7 * 256 * Hn];        // fp16

// ---------------- helpers ----------------
__device__ __forceinline__ uint32_t smem_u32(const void* p) {
    uint32_t a;
    asm("{ .reg .u64 t; cvta.to.shared.u64 t, %1; cvt.u32.u64 %0, t; }" : "=r"(a) : "l"(p));
    return a;
}
__device__ __forceinline__ void cpa16(uint32_t dst, const void* src, int sz) {
    asm volatile("cp.async.cg.shared.global [%0], [%1], 16, %2;"
                 :: "r"(dst), "l"(src), "r"(sz) : "memory");
}
#define CP_COMMIT() asm volatile("cp.async.commit_group;" ::: "memory")
#define CP_WAIT(n)  asm volatile("cp.async.wait_group %0;" :: "n"(n) : "memory")

__device__ __forceinline__ void mma_h(float* d,
    uint32_t a0, uint32_t a1, uint32_t a2, uint32_t a3,
    uint32_t b0, uint32_t b1) {
    asm volatile(
        "mma.sync.aligned.m16n8k16.row.col.f32.f16.f16.f32 "
        "{%0,%1,%2,%3}, {%4,%5,%6,%7}, {%8,%9}, {%0,%1,%2,%3};"
        : "+f"(d[0]), "+f"(d[1]), "+f"(d[2]), "+f"(d[3])
        : "r"(a0), "r"(a1), "r"(a2), "r"(a3), "r"(b0), "r"(b1));
}

#define SWZ(x)  ((x) ^ (((x) >> 3) & 0x70))   // 128B rows
#define SWZ2(x) ((x) ^ (((x) >> 5) & 0x70))   // 512B rows

__device__ __forceinline__ unsigned short f2h(float x) {
    unsigned short u; asm("cvt.rn.f16.f32 %0, %1;" : "=h"(u) : "f"(x)); return u;
}

// ---------------- bucketing ----------------
__global__ void k_zero() {
    int t = threadIdx.x;
    if (t < NBn) { g_counts[t] = 0; g_cursor[t] = 0; }
}
__global__ void k_count(const int* __restrict__ cmd) {
    __shared__ int loc[NBn];
    if (threadIdx.x < NBn) loc[threadIdx.x] = 0;
    __syncthreads();
    int i = blockIdx.x * blockDim.x + threadIdx.x;
    if (i < Bn) atomicAdd(&loc[cmd[i] - 1], 1);
    __syncthreads();
    if (threadIdx.x < NBn) atomicAdd(&g_counts[threadIdx.x], loc[threadIdx.x]);
}
__global__ void k_scan() {
    int acc = 0;
    for (int g = 0; g < NBn; g++) {
        g_poff[g] = acc;
        acc += (g_counts[g] + TM - 1) & ~(TM - 1);
    }
    g_poff[NBn] = acc;
}
__global__ void k_scatter(const int* __restrict__ cmd) {
    int i = blockIdx.x * blockDim.x + threadIdx.x;
    if (i < Bn) {
        int g = cmd[i] - 1;
        int idx = atomicAdd(&g_cursor[g], 1);
        g_perm[g_poff[g] + idx] = i;
    }
}

// -------- speed_in piecewise-linear precompute (single CTA) ---------------
__global__ __launch_bounds__(256) void k_pwprep(
    const float* __restrict__ w1, const float* __restrict__ b1,
    const float* __restrict__ W2, const float* __restrict__ b2)
{
    __shared__ float w1s[256], b1s[256], thr[256];
    __shared__ int sidx[256];
    const float INF = __int_as_float(0x7f800000);
    int t = threadIdx.x;
    float w = w1[t], b = b1[t];
    w1s[t] = w; b1s[t] = b;
    float tv = (w != 0.f) ? (-b / w) : INF;
    thr[t] = tv;
    __syncthreads();
    int r = 0;
    for (int k = 0; k < 256; k++) {
        float tk = thr[k];
        if (tk < tv || (tk == tv && k < t)) r++;
    }
    sidx[r] = t;
    g_thr[r] = tv;
    __syncthreads();
    if (t < 128) {
        int c = t;
        float u = 0.f, v = b2[c];
        for (int j = 0; j < 256; j++) {
            float wj = w1s[j];
            bool act = (wj < 0.f) || (wj == 0.f && b1s[j] > 0.f);
            if (act) {
                float w2 = W2[j * SLn + c];
                u += wj * w2; v += b1s[j] * w2;
            }
        }
        g_pw[c] = u; g_pw[128 + c] = v;
        for (int i = 1; i <= 256; i++) {
            int j = sidx[i - 1];
            float wj = w1s[j];
            if (wj != 0.f) {
                float w2 = W2[j * SLn + c];
                float sg = (wj > 0.f) ? 1.f : -1.f;
                u += sg * wj * w2; v += sg * b1s[j] * w2;
            }
            g_pw[i * 256 + c] = u; g_pw[i * 256 + 128 + c] = v;
        }
    }
}

// -------- convert A rows (emb || speed_in(speed)) -> fp16 [B,640] ---------
__global__ __launch_bounds__(256) void k_convA(
    const float* __restrict__ emb, const float* __restrict__ speed)
{
    size_t quad = (size_t)blockIdx.x * 256 + threadIdx.x;
    size_t b = quad / 160;
    int d0 = (int)(quad - b * 160) * 4;
    float4 v;
    if (d0 < En) {
        v = *(const float4*)(emb + b * En + d0);
    } else {
        float spd = speed[b];
        int lo = 0, hi = 256;
        while (lo < hi) {
            int mid = (lo + hi) >> 1;
            if (g_thr[mid] < spd) lo = mid + 1; else hi = mid;
        }
        const float* pw = g_pw + (size_t)lo * 256 + (d0 - En);
        v.x = spd * pw[0] + pw[128];
        v.y = spd * pw[1] + pw[129];
        v.z = spd * pw[2] + pw[130];
        v.w = spd * pw[3] + pw[131];
    }
    uint2 H;
    H.x = ((uint32_t)f2h(v.y) << 16) | f2h(v.x);
    H.y = ((uint32_t)f2h(v.w) << 16) | f2h(v.z);
    *(uint2*)&g_A[b * Dn + d0] = H;
}

// -------- transpose + convert weights: [Kd,256] -> [7][256][Kd] fp16 ------
__global__ __launch_bounds__(256) void k_convW(
    const float* __restrict__ srcB, const float* __restrict__ srcS,
    unsigned short* __restrict__ dst, int Kd)
{
    __shared__ float tile[32][33];
    int ntk = Kd / 32;
    int bid = blockIdx.x;
    int g = bid / (ntk * 8);
    int rem = bid - g * ntk * 8;
    int kt = rem / 8, nt = rem - (rem / 8) * 8;
    const float* src = (g < 6) ? srcB + (size_t)g * Kd * 256 : srcS;
    int tid = threadIdx.x;
#pragma unroll
    for (int i = 0; i < 4; i++) {
        int idx = i * 256 + tid;
        int kk = idx >> 5, nn = idx & 31;
        tile[kk][nn] = src[(size_t)(kt * 32 + kk) * 256 + nt * 32 + nn];
    }
    __syncthreads();
#pragma unroll
    for (int i = 0; i < 4; i++) {
        int idx = i * 256 + tid;
        int nn = idx >> 5, kk = idx & 31;
        size_t o = ((size_t)g * 256 + nt * 32 + nn) * Kd + kt * 32 + kk;
        dst[o] = f2h(tile[kk][nn]);
    }
}

// ---------------- fused MLP via mma.sync (fp16 HMMA, 1-term) --------------
// Layer-1 stages: [0..49152) and [49152..98304)  (A 16KB + B 32KB each)
// A2 activations:  [98304..163840)               (128 x 512B)
// Layer-2 B stages REUSE the layer-1 staging region after it drains:
//   stage 0 at [0..32768), stage 1 at [32768..65536)
#define S_STG(s)  ((uint32_t)(s) * 49152u)
#define S_A1(s)   (S_STG(s))
#define S_B1(s)   (S_STG(s) + 16384u)
#define S_A2      98304u
#define S_B2(s)   ((uint32_t)(s) * 32768u)
#define S_BIAS1  196608u
#define S_BIAS2  197632u
#define S_W3     198656u
#define S_B3     201728u
#define S_ROWS   201744u
#define S_SRED   202256u
#define SMEM_TOT 203808

__global__ __launch_bounds__(512, 1) void k_mlp(
    const float* __restrict__ bb1, const float* __restrict__ bb2,
    const float* __restrict__ bW3, const float* __restrict__ bb3,
    const float* __restrict__ so_b1, const float* __restrict__ so_b2,
    const float* __restrict__ so_W3, const float* __restrict__ so_b3,
    float* __restrict__ out)
{
    extern __shared__ unsigned char sm[];
    int tid = threadIdx.x;
    int wid = tid >> 5, lane = tid & 31;
    int wm = wid & 3, wn = wid >> 2;
    int bid = blockIdx.x;
    bool is_speed = (bid < Bn / TM);
    int g, row0;
    if (is_speed) { g = 6; row0 = bid * TM; }
    else {
        int t = bid - Bn / TM;
        row0 = t * TM;
        if (row0 >= g_poff[NBn]) return;
        g = 0;
#pragma unroll
        for (int i = 0; i < NBn - 1; i++) if (row0 >= g_poff[i + 1]) g = i + 1;
    }
    uint32_t sb = smem_u32(sm);
    float* bias1s = (float*)(sm + S_BIAS1);
    float* bias2s = (float*)(sm + S_BIAS2);
    float* w3s    = (float*)(sm + S_W3);
    float* b3s    = (float*)(sm + S_B3);
    int*   rows_s = (int*)(sm + S_ROWS);
    float* sred   = (float*)(sm + S_SRED);

    if (tid < TM) {
        if (is_speed) rows_s[tid] = row0 + tid;
        else {
            int base = g_poff[g], cnt = g_counts[g];
            int l = row0 - base + tid;
            rows_s[tid] = (l < cnt) ? g_perm[base + l] : -1;
        }
    }
    if (tid < Hn) {
        bias1s[tid] = is_speed ? so_b1[tid] : bb1[g * Hn + tid];
        bias2s[tid] = is_speed ? so_b2[tid] : bb2[g * Hn + tid];
    }
    if (is_speed) { if (tid < Hn) w3s[tid] = so_W3[tid]; }
    else { for (int i = tid; i < Hn * 3; i += 512) w3s[i] = bW3[g * Hn * 3 + i]; }
    if (tid < (is_speed ? 1 : 3)) b3s[tid] = is_speed ? so_b3[0] : bb3[g * 3 + tid];
    if (tid < TM * 3) sred[tid] = 0.f;
    __syncthreads();

    auto fill1 = [&](int s, int c) {
        // A fp16: 128 rows x 8 x 16B
#pragma unroll
        for (int it = 0; it < 2; ++it) {
            int idx = it * 512 + tid;
            int r = idx >> 3, seg = idx & 7;
            int orow = rows_s[r];
            size_t go = (orow >= 0) ? ((size_t)orow * Dn + c * 64 + seg * 8) : 0;
            int sz = (orow >= 0) ? 16 : 0;
            uint32_t sw = SWZ((uint32_t)(r * 128 + seg * 16));
            cpa16(sb + S_A1(s) + sw, g_A + go, sz);
        }
        // B fp16: 256 rows x 8 x 16B
#pragma unroll
        for (int it = 0; it < 4; ++it) {
            int idx = it * 512 + tid;
            int n = idx >> 3, seg = idx & 7;
            size_t go = ((size_t)g * 256 + n) * Dn + c * 64 + seg * 8;
            uint32_t sw = SWZ((uint32_t)(n * 128 + seg * 16));
            cpa16(sb + S_B1(s) + sw, g_W1 + go, 16);
        }
        CP_COMMIT();
    };
    auto fill2 = [&](int c2) {
        int s2 = c2 & 1;
#pragma unroll
        for (int it = 0; it < 4; ++it) {
            int idx = it * 512 + tid;
            int n = idx >> 3, seg = idx & 7;
            size_t go = ((size_t)g * 256 + n) * Hn + c2 * 64 + seg * 8;
            uint32_t sw = SWZ((uint32_t)(n * 128 + seg * 16));
            cpa16(sb + S_B2(s2) + sw, g_W2 + go, 16);
        }
        CP_COMMIT();
    };

    float acc[2][8][4];
#pragma unroll
    for (int m = 0; m < 2; m++)
#pragma unroll
        for (int n = 0; n < 8; n++)
#pragma unroll
            for (int j = 0; j < 4; j++) acc[m][n][j] = 0.f;

    // ================= layer 1: 10 chunks of k=64, double-buffered =========
    fill1(0, 0);
    fill1(1, 1);
    for (int c = 0; c < 10; ++c) {
        int s = c & 1;
        if (c < 9) { CP_WAIT(1); } else { CP_WAIT(0); }
        __syncthreads();
        uint32_t aB = S_A1(s), bB = S_B1(s);
#pragma unroll
        for (int ks = 0; ks < 4; ++ks) {
            uint32_t cb = (uint32_t)(ks * 32 + (lane & 3) * 4);
            uint32_t ah[2][4];
#pragma unroll
            for (int m = 0; m < 2; m++) {
                uint32_t r = (uint32_t)(wm * 32 + m * 16 + (lane >> 2));
                ah[m][0] = *(uint32_t*)(sm + aB + SWZ(r * 128 + cb));
                ah[m][1] = *(uint32_t*)(sm + aB + SWZ((r + 8) * 128 + cb));
                ah[m][2] = *(uint32_t*)(sm + aB + SWZ(r * 128 + cb + 16));
                ah[m][3] = *(uint32_t*)(sm + aB + SWZ((r + 8) * 128 + cb + 16));
            }
#pragma unroll
            for (int nt = 0; nt < 8; ++nt) {
                uint32_t n = (uint32_t)(wn * 64 + nt * 8 + (lane >> 2));
                uint32_t bh0 = *(uint32_t*)(sm + bB + SWZ(n * 128 + cb));
                uint32_t bh1 = *(uint32_t*)(sm + bB + SWZ(n * 128 + cb + 16));
#pragma unroll
                for (int m = 0; m < 2; m++)
                    mma_h(acc[m][nt], ah[m][0], ah[m][1], ah[m][2], ah[m][3], bh0, bh1);
            }
        }
        __syncthreads();
        if (c + 2 < 10) fill1(s, c + 2);
    }

    // layer-1 staging region is drained (final CP_WAIT(0) + syncthreads);
    // prefetch both layer-2 weight stages into it
    fill2(0);
    fill2(1);

    // ===== epilogue 1: relu(D+b1) -> fp16 into A2 (512B rows, SWZ2) ========
#pragma unroll
    for (int m = 0; m < 2; m++) {
#pragma unroll
        for (int half = 0; half < 2; half++) {
            uint32_t r = (uint32_t)(wm * 32 + m * 16 + half * 8 + (lane >> 2));
#pragma unroll
            for (int nt = 0; nt < 8; ++nt) {
                int c0 = wn * 64 + nt * 8 + (lane & 3) * 2;
                float v0 = fmaxf(acc[m][nt][half * 2 + 0] + bias1s[c0], 0.f);
                float v1 = fmaxf(acc[m][nt][half * 2 + 1] + bias1s[c0 + 1], 0.f);
                uint32_t byte = SWZ2((uint32_t)(r * 512 + c0 * 2));
                *(uint32_t*)(sm + S_A2 + byte) = ((uint32_t)f2h(v1) << 16) | f2h(v0);
            }
        }
    }
#pragma unroll
    for (int m = 0; m < 2; m++)
#pragma unroll
        for (int n = 0; n < 8; n++)
#pragma unroll
            for (int j = 0; j < 4; j++) acc[m][n][j] = 0.f;

    // ================= layer 2: 4 chunks of k=64, double-buffered ==========
    for (int c2 = 0; c2 < 4; ++c2) {
        int s2 = c2 & 1;
        if (c2 < 3) { CP_WAIT(1); } else { CP_WAIT(0); }
        __syncthreads();
#pragma unroll
        for (int ks = 0; ks < 4; ++ks) {
            uint32_t kg = (uint32_t)(c2 * 64 + ks * 16 + (lane & 3) * 2) * 2;
            uint32_t cb = (uint32_t)(ks * 32 + (lane & 3) * 4);
            uint32_t ah[2][4];
#pragma unroll
            for (int m = 0; m < 2; m++) {
                uint32_t r = (uint32_t)(wm * 32 + m * 16 + (lane >> 2));
                ah[m][0] = *(uint32_t*)(sm + S_A2 + SWZ2(r * 512 + kg));
                ah[m][1] = *(uint32_t*)(sm + S_A2 + SWZ2((r + 8) * 512 + kg));
                ah[m][2] = *(uint32_t*)(sm + S_A2 + SWZ2(r * 512 + kg + 16));
                ah[m][3] = *(uint32_t*)(sm + S_A2 + SWZ2((r + 8) * 512 + kg + 16));
            }
#pragma unroll
            for (int nt = 0; nt < 8; ++nt) {
                uint32_t n = (uint32_t)(wn * 64 + nt * 8 + (lane >> 2));
                uint32_t bh0 = *(uint32_t*)(sm + S_B2(s2) + SWZ(n * 128 + cb));
                uint32_t bh1 = *(uint32_t*)(sm + S_B2(s2) + SWZ(n * 128 + cb + 16));
#pragma unroll
                for (int m = 0; m < 2; m++)
                    mma_h(acc[m][nt], ah[m][0], ah[m][1], ah[m][2], ah[m][3], bh0, bh1);
            }
        }
        __syncthreads();
        if (c2 + 2 < 4) fill2(c2 + 2);
    }

    // ===== epilogue 2: relu(D+b2), layer-3 dot, reduce, activate, scatter ==
#pragma unroll
    for (int m = 0; m < 2; m++) {
#pragma unroll
        for (int half = 0; half < 2; half++) {
            int rl = wm * 32 + m * 16 + half * 8 + (lane >> 2);
            float p0 = 0.f, p1 = 0.f, p2 = 0.f;
#pragma unroll
            for (int nt = 0; nt < 8; ++nt) {
                int c0 = wn * 64 + nt * 8 + (lane & 3) * 2;
                float v0 = fmaxf(acc[m][nt][half * 2 + 0] + bias2s[c0], 0.f);
                float v1 = fmaxf(acc[m][nt][half * 2 + 1] + bias2s[c0 + 1], 0.f);
                if (is_speed) {
                    p0 += v0 * w3s[c0] + v1 * w3s[c0 + 1];
                } else {
                    p0 += v0 * w3s[c0 * 3]     + v1 * w3s[(c0 + 1) * 3];
                    p1 += v0 * w3s[c0 * 3 + 1] + v1 * w3s[(c0 + 1) * 3 + 1];
                    p2 += v0 * w3s[c0 * 3 + 2] + v1 * w3s[(c0 + 1) * 3 + 2];
                }
            }
#pragma unroll
            for (int d = 1; d < 4; d <<= 1) {
                p0 += __shfl_xor_sync(0xffffffffu, p0, d);
                p1 += __shfl_xor_sync(0xffffffffu, p1, d);
                p2 += __shfl_xor_sync(0xffffffffu, p2, d);
            }
            if ((lane & 3) == 0) {
                if (is_speed) atomicAdd(&sred[rl], p0);
                else {
                    atomicAdd(&sred[rl * 3 + 0], p0);
                    atomicAdd(&sred[rl * 3 + 1], p1);
                    atomicAdd(&sred[rl * 3 + 2], p2);
                }
            }
        }
    }
    __syncthreads();
    if (tid < TM) {
        int orow = rows_s[tid];
        if (is_speed) {
            out[(size_t)Bn * 3 + orow] = sred[tid] + b3s[0];
        } else if (orow >= 0) {
            float s0 = sred[tid * 3 + 0] + b3s[0];
            float s1 = sred[tid * 3 + 1] + b3s[1];
            float s2 = sred[tid * 3 + 2] + b3s[2];
            out[(size_t)orow * 3 + 0] = 1.f / (1.f + expf(-s0));
            out[(size_t)orow * 3 + 1] = 1.f / (1.f + expf(-s1));
            out[(size_t)orow * 3 + 2] = 1.f / (1.f + expf(-s2));
        }
    }
}

// ---------------- launcher ----------------
extern "C" void kernel_launch(void* const* d_in, const int* in_sizes, int n_in,
                              void* d_out, int out_size) {
    const float* embedding = (const float*)d_in[0];
    const float* speed     = (const float*)d_in[1];
    const int*   command   = (const int*)d_in[2];
    const float* si_W1 = (const float*)d_in[3];
    const float* si_b1 = (const float*)d_in[4];
    const float* si_W2 = (const float*)d_in[5];
    const float* si_b2 = (const float*)d_in[6];
    const float* bW1   = (const float*)d_in[7];
    const float* bb1   = (const float*)d_in[8];
    const float* bW2   = (const float*)d_in[9];
    const float* bb2   = (const float*)d_in[10];
    const float* bW3   = (const float*)d_in[11];
    const float* bb3   = (const float*)d_in[12];
    const float* so_W1 = (const float*)d_in[13];
    const float* so_b1 = (const float*)d_in[14];
    const float* so_W2 = (const float*)d_in[15];
    const float* so_b2 = (const float*)d_in[16];
    const float* so_W3 = (const float*)d_in[17];
    const float* so_b3 = (const float*)d_in[18];
    float* out = (float*)d_out;

    unsigned short *w1p, *w2p;
    cudaGetSymbolAddress((void**)&w1p, g_W1);
    cudaGetSymbolAddress((void**)&w2p, g_W2);

    cudaFuncSetAttribute(k_mlp, cudaFuncAttributeMaxDynamicSharedMemorySize, SMEM_TOT);

    k_zero<<<1, 32>>>();
    k_count<<<Bn / 256, 256>>>(command);
    k_scan<<<1, 1>>>();
    k_scatter<<<Bn / 256, 256>>>(command);
    k_pwprep<<<1, 256>>>(si_W1, si_b1, si_W2, si_b2);
    k_convA<<<(int)(((size_t)Bn * Dn / 4) / 256), 256>>>(embedding, speed);
    k_convW<<<7 * (Dn / 32) * 8, 256>>>(bW1, so_W1, w1p, Dn);
    k_convW<<<7 * (Hn / 32) * 8, 256>>>(bW2, so_W2, w2p, Hn);

    int branch_tiles = (Bn + NBn * (TM - 1)) / TM + 1;   // 518
    k_mlp<<<Bn / TM + branch_tiles, 512, SMEM_TOT>>>(
        bb1, bb2, bW3, bb3, so_b1, so_b2, so_W3, so_b3, out);
}

// round 14
// speedup vs baseline: 7.6896x; 1.0496x over previous
#include <cuda_runtime.h>
#include <cuda_fp16.h>
#include <math.h>
#include <stdint.h>

#define Bn  65536
#define En  512
#define SLn 128
#define Hn  256
#define NBn 6
#define Dn  640
#define TM  128

// ---------------- scratch (static device globals; no allocations) ---------
__device__ int   g_perm[Bn + NBn * TM];
__device__ int   g_counts[NBn];
__device__ int   g_poff[NBn + 1];
__device__ int   g_bhist[256 * NBn];
__device__ int   g_boff[256 * NBn];
__device__ float g_thr[256];             // sorted relu breakpoints of speed_in
__device__ float g_pw[257 * 256];        // per-interval [u(128) | v(128)]
__device__ __align__(16) unsigned short g_A[(size_t)Bn * Dn];      // fp16
__device__ __align__(16) unsigned short g_W1[7 * 256 * Dn];        // fp16
__device__ __align__(16) unsigned short g_W2[7 * 256 * Hn];        // fp16

// ---------------- helpers ----------------
__device__ __forceinline__ uint32_t smem_u32(const void* p) {
    uint32_t a;
    asm("{ .reg .u64 t; cvta.to.shared.u64 t, %1; cvt.u32.u64 %0, t; }" : "=r"(a) : "l"(p));
    return a;
}
__device__ __forceinline__ void cpa16(uint32_t dst, const void* src, int sz) {
    asm volatile("cp.async.cg.shared.global [%0], [%1], 16, %2;"
                 :: "r"(dst), "l"(src), "r"(sz) : "memory");
}
#define CP_COMMIT() asm volatile("cp.async.commit_group;" ::: "memory")
#define CP_WAIT(n)  asm volatile("cp.async.wait_group %0;" :: "n"(n) : "memory")

__device__ __forceinline__ void mma_h(float* d,
    uint32_t a0, uint32_t a1, uint32_t a2, uint32_t a3,
    uint32_t b0, uint32_t b1) {
    asm volatile(
        "mma.sync.aligned.m16n8k16.row.col.f32.f16.f16.f32 "
        "{%0,%1,%2,%3}, {%4,%5,%6,%7}, {%8,%9}, {%0,%1,%2,%3};"
        : "+f"(d[0]), "+f"(d[1]), "+f"(d[2]), "+f"(d[3])
        : "r"(a0), "r"(a1), "r"(a2), "r"(a3), "r"(b0), "r"(b1));
}

#define SWZ(x)  ((x) ^ (((x) >> 3) & 0x70))   // 128B rows
#define SWZ2(x) ((x) ^ (((x) >> 5) & 0x70))   // 512B rows

__device__ __forceinline__ unsigned short f2h(float x) {
    unsigned short u; asm("cvt.rn.f16.f32 %0, %1;" : "=h"(u) : "f"(x)); return u;
}

// ============ K0: per-block command histogram (no zeroing needed) =========
__global__ __launch_bounds__(256) void k_hist(const int* __restrict__ cmd) {
    __shared__ int loc[NBn];
    int t = threadIdx.x;
    if (t < NBn) loc[t] = 0;
    __syncthreads();
    atomicAdd(&loc[cmd[blockIdx.x * 256 + t] - 1], 1);
    __syncthreads();
    if (t < NBn) g_bhist[blockIdx.x * NBn + t] = loc[t];
}

// ============ K1: block0 = scan, block1 = speed_in pw precompute ==========
__global__ __launch_bounds__(256) void k_scanprep(
    const float* __restrict__ w1, const float* __restrict__ b1,
    const float* __restrict__ W2, const float* __restrict__ b2)
{
    int t = threadIdx.x;
    if (blockIdx.x == 0) {
        // totals
        if (t < NBn) {
            int s = 0;
            for (int i = 0; i < 256; i++) s += g_bhist[i * NBn + t];
            g_counts[t] = s;
        }
        __syncthreads();
        if (t == 0) {
            int acc = 0;
            for (int g = 0; g < NBn; g++) {
                g_poff[g] = acc;
                acc += (g_counts[g] + TM - 1) & ~(TM - 1);
            }
            g_poff[NBn] = acc;
        }
        __syncthreads();
        if (t < NBn) {
            int run = g_poff[t];
            for (int i = 0; i < 256; i++) {
                g_boff[i * NBn + t] = run;
                run += g_bhist[i * NBn + t];
            }
        }
        return;
    }
    // ---- pwprep ----
    __shared__ float w1s[256], b1s[256], thr[256];
    __shared__ int sidx[256];
    const float INF = __int_as_float(0x7f800000);
    float w = w1[t], b = b1[t];
    w1s[t] = w; b1s[t] = b;
    float tv = (w != 0.f) ? (-b / w) : INF;
    thr[t] = tv;
    __syncthreads();
    int r = 0;
    for (int k = 0; k < 256; k++) {
        float tk = thr[k];
        if (tk < tv || (tk == tv && k < t)) r++;
    }
    sidx[r] = t;
    g_thr[r] = tv;
    __syncthreads();
    if (t < 128) {
        int c = t;
        float u = 0.f, v = b2[c];
        for (int j = 0; j < 256; j++) {
            float wj = w1s[j];
            bool act = (wj < 0.f) || (wj == 0.f && b1s[j] > 0.f);
            if (act) {
                float w2 = W2[j * SLn + c];
                u += wj * w2; v += b1s[j] * w2;
            }
        }
        g_pw[c] = u; g_pw[128 + c] = v;
        for (int i = 1; i <= 256; i++) {
            int j = sidx[i - 1];
            float wj = w1s[j];
            if (wj != 0.f) {
                float w2 = W2[j * SLn + c];
                float sg = (wj > 0.f) ? 1.f : -1.f;
                u += sg * wj * w2; v += sg * b1s[j] * w2;
            }
            g_pw[i * 256 + c] = u; g_pw[i * 256 + 128 + c] = v;
        }
    }
}

// ============ K2: fused convA | scatter | convW1 | convW2 =================
#define GA_CONVA 40960                       // Bn*Dn/4/256
#define GA_SCAT  (GA_CONVA + 256)
#define GA_CW1   (GA_SCAT + 7 * (Dn / 32) * 8)   // +1120
#define GA_END   (GA_CW1 + 7 * (Hn / 32) * 8)    // +448

__global__ __launch_bounds__(256) void k_prep(
    const float* __restrict__ emb, const float* __restrict__ speed,
    const int* __restrict__ cmd,
    const float* __restrict__ bW1, const float* __restrict__ soW1,
    const float* __restrict__ bW2, const float* __restrict__ soW2)
{
    __shared__ float tile[32][33];
    __shared__ int loc[NBn];
    int tid = threadIdx.x;
    int bid = blockIdx.x;

    if (bid < GA_CONVA) {
        // ---- convA: (emb || speed_in) -> fp16 ----
        size_t quad = (size_t)bid * 256 + tid;
        size_t b = quad / 160;
        int d0 = (int)(quad - b * 160) * 4;
        float4 v;
        if (d0 < En) {
            v = *(const float4*)(emb + b * En + d0);
        } else {
            float spd = speed[b];
            int lo = 0, hi = 256;
            while (lo < hi) {
                int mid = (lo + hi) >> 1;
                if (g_thr[mid] < spd) lo = mid + 1; else hi = mid;
            }
            const float* pw = g_pw + (size_t)lo * 256 + (d0 - En);
            v.x = spd * pw[0] + pw[128];
            v.y = spd * pw[1] + pw[129];
            v.z = spd * pw[2] + pw[130];
            v.w = spd * pw[3] + pw[131];
        }
        uint2 H;
        H.x = ((uint32_t)f2h(v.y) << 16) | f2h(v.x);
        H.y = ((uint32_t)f2h(v.w) << 16) | f2h(v.z);
        *(uint2*)&g_A[b * Dn + d0] = H;
        return;
    }
    if (bid < GA_SCAT) {
        // ---- scatter using precomputed block offsets ----
        int cta = bid - GA_CONVA;
        if (tid < NBn) loc[tid] = g_boff[cta * NBn + tid];
        __syncthreads();
        int i = cta * 256 + tid;
        int g = cmd[i] - 1;
        int idx = atomicAdd(&loc[g], 1);
        g_perm[idx] = i;
        return;
    }
    // ---- convW: transpose + fp16 ----
    const float* srcB; const float* srcS; unsigned short* dst; int Kd; int rel;
    if (bid < GA_CW1) { srcB = bW1; srcS = soW1; dst = g_W1; Kd = Dn; rel = bid - GA_SCAT; }
    else              { srcB = bW2; srcS = soW2; dst = g_W2; Kd = Hn; rel = bid - GA_CW1; }
    int ntk = Kd / 32;
    int g = rel / (ntk * 8);
    int rem = rel - g * ntk * 8;
    int kt = rem / 8, nt = rem - (rem / 8) * 8;
    const float* src = (g < 6) ? srcB + (size_t)g * Kd * 256 : srcS;
#pragma unroll
    for (int i = 0; i < 4; i++) {
        int idx = i * 256 + tid;
        int kk = idx >> 5, nn = idx & 31;
        tile[kk][nn] = src[(size_t)(kt * 32 + kk) * 256 + nt * 32 + nn];
    }
    __syncthreads();
#pragma unroll
    for (int i = 0; i < 4; i++) {
        int idx = i * 256 + tid;
        int nn = idx >> 5, kk = idx & 31;
        size_t o = ((size_t)g * 256 + nt * 32 + nn) * Kd + kt * 32 + kk;
        dst[o] = f2h(tile[kk][nn]);
    }
}

// ---------------- fused MLP via mma.sync (fp16 HMMA, 1-term) --------------
// Layer-1: 3 stages x 48KB at [0..147456). A2: [147456..212992).
// Layer-2 B: 3 stages x 32KB reusing [0..98304) after layer-1 drains.
#define S_STG(s)  ((uint32_t)(s) * 49152u)
#define S_A1(s)   (S_STG(s))
#define S_B1(s)   (S_STG(s) + 16384u)
#define S_A2      147456u
#define S_B2(s)   ((uint32_t)(s) * 32768u)
#define S_BIAS1  212992u
#define S_BIAS2  214016u
#define S_W3     215040u
#define S_B3     218112u
#define S_ROWS   218128u
#define S_SRED   218640u
#define SMEM_TOT 220176

__global__ __launch_bounds__(512, 1) void k_mlp(
    const float* __restrict__ bb1, const float* __restrict__ bb2,
    const float* __restrict__ bW3, const float* __restrict__ bb3,
    const float* __restrict__ so_b1, const float* __restrict__ so_b2,
    const float* __restrict__ so_W3, const float* __restrict__ so_b3,
    float* __restrict__ out)
{
    extern __shared__ unsigned char sm[];
    int tid = threadIdx.x;
    int wid = tid >> 5, lane = tid & 31;
    int wm = wid & 3, wn = wid >> 2;
    int bid = blockIdx.x;
    bool is_speed = (bid < Bn / TM);
    int g, row0;
    if (is_speed) { g = 6; row0 = bid * TM; }
    else {
        int t = bid - Bn / TM;
        row0 = t * TM;
        if (row0 >= g_poff[NBn]) return;
        g = 0;
#pragma unroll
        for (int i = 0; i < NBn - 1; i++) if (row0 >= g_poff[i + 1]) g = i + 1;
    }
    uint32_t sb = smem_u32(sm);
    float* bias1s = (float*)(sm + S_BIAS1);
    float* bias2s = (float*)(sm + S_BIAS2);
    float* w3s    = (float*)(sm + S_W3);
    float* b3s    = (float*)(sm + S_B3);
    int*   rows_s = (int*)(sm + S_ROWS);
    float* sred   = (float*)(sm + S_SRED);

    if (tid < TM) {
        if (is_speed) rows_s[tid] = row0 + tid;
        else {
            int base = g_poff[g], cnt = g_counts[g];
            int l = row0 - base + tid;
            rows_s[tid] = (l < cnt) ? g_perm[base + l] : -1;
        }
    }
    if (tid < Hn) {
        bias1s[tid] = is_speed ? so_b1[tid] : bb1[g * Hn + tid];
        bias2s[tid] = is_speed ? so_b2[tid] : bb2[g * Hn + tid];
    }
    if (is_speed) { if (tid < Hn) w3s[tid] = so_W3[tid]; }
    else { for (int i = tid; i < Hn * 3; i += 512) w3s[i] = bW3[g * Hn * 3 + i]; }
    if (tid < (is_speed ? 1 : 3)) b3s[tid] = is_speed ? so_b3[0] : bb3[g * 3 + tid];
    if (tid < TM * 3) sred[tid] = 0.f;
    __syncthreads();

    auto fill1 = [&](int s, int c) {
#pragma unroll
        for (int it = 0; it < 2; ++it) {
            int idx = it * 512 + tid;
            int r = idx >> 3, seg = idx & 7;
            int orow = rows_s[r];
            size_t go = (orow >= 0) ? ((size_t)orow * Dn + c * 64 + seg * 8) : 0;
            int sz = (orow >= 0) ? 16 : 0;
            uint32_t sw = SWZ((uint32_t)(r * 128 + seg * 16));
            cpa16(sb + S_A1(s) + sw, g_A + go, sz);
        }
#pragma unroll
        for (int it = 0; it < 4; ++it) {
            int idx = it * 512 + tid;
            int n = idx >> 3, seg = idx & 7;
            size_t go = ((size_t)g * 256 + n) * Dn + c * 64 + seg * 8;
            uint32_t sw = SWZ((uint32_t)(n * 128 + seg * 16));
            cpa16(sb + S_B1(s) + sw, g_W1 + go, 16);
        }
        CP_COMMIT();
    };
    auto fill2 = [&](int c2) {
        int s2 = c2 % 3;
#pragma unroll
        for (int it = 0; it < 4; ++it) {
            int idx = it * 512 + tid;
            int n = idx >> 3, seg = idx & 7;
            size_t go = ((size_t)g * 256 + n) * Hn + c2 * 64 + seg * 8;
            uint32_t sw = SWZ((uint32_t)(n * 128 + seg * 16));
            cpa16(sb + S_B2(s2) + sw, g_W2 + go, 16);
        }
        CP_COMMIT();
    };

    float acc[2][8][4];
#pragma unroll
    for (int m = 0; m < 2; m++)
#pragma unroll
        for (int n = 0; n < 8; n++)
#pragma unroll
            for (int j = 0; j < 4; j++) acc[m][n][j] = 0.f;

    // ===== layer 1: 10 chunks of k=64, 3-stage, ONE barrier per chunk =====
    fill1(0, 0); fill1(1, 1); fill1(2, 2);
    for (int c = 0; c < 10; ++c) {
        if (c == 0) { CP_WAIT(2); }
        else if (c <= 8) { CP_WAIT(1); }
        else { CP_WAIT(0); }
        __syncthreads();   // stage c ready everywhere; stage (c-1)%3 drained
        if (c >= 1 && c + 2 <= 9) fill1((c - 1) % 3, c + 2);
        int s = c % 3;
        uint32_t aB = S_A1(s), bB = S_B1(s);
#pragma unroll
        for (int ks = 0; ks < 4; ++ks) {
            uint32_t cb = (uint32_t)(ks * 32 + (lane & 3) * 4);
            uint32_t ah[2][4];
#pragma unroll
            for (int m = 0; m < 2; m++) {
                uint32_t r = (uint32_t)(wm * 32 + m * 16 + (lane >> 2));
                ah[m][0] = *(uint32_t*)(sm + aB + SWZ(r * 128 + cb));
                ah[m][1] = *(uint32_t*)(sm + aB + SWZ((r + 8) * 128 + cb));
                ah[m][2] = *(uint32_t*)(sm + aB + SWZ(r * 128 + cb + 16));
                ah[m][3] = *(uint32_t*)(sm + aB + SWZ((r + 8) * 128 + cb + 16));
            }
#pragma unroll
            for (int nt = 0; nt < 8; ++nt) {
                uint32_t n = (uint32_t)(wn * 64 + nt * 8 + (lane >> 2));
                uint32_t bh0 = *(uint32_t*)(sm + bB + SWZ(n * 128 + cb));
                uint32_t bh1 = *(uint32_t*)(sm + bB + SWZ(n * 128 + cb + 16));
#pragma unroll
                for (int m = 0; m < 2; m++)
                    mma_h(acc[m][nt], ah[m][0], ah[m][1], ah[m][2], ah[m][3], bh0, bh1);
            }
        }
    }
    __syncthreads();   // all warps done reading layer-1 stages

    // prefetch all 3 layer-2 B stages into the freed region (chunks 0..2)
    fill2(0); fill2(1); fill2(2);

    // ===== epilogue 1: relu(D+b1) -> fp16 into A2 (512B rows, SWZ2) ========
#pragma unroll
    for (int m = 0; m < 2; m++) {
#pragma unroll
        for (int half = 0; half < 2; half++) {
            uint32_t r = (uint32_t)(wm * 32 + m * 16 + half * 8 + (lane >> 2));
#pragma unroll
            for (int nt = 0; nt < 8; ++nt) {
                int c0 = wn * 64 + nt * 8 + (lane & 3) * 2;
                float v0 = fmaxf(acc[m][nt][half * 2 + 0] + bias1s[c0], 0.f);
                float v1 = fmaxf(acc[m][nt][half * 2 + 1] + bias1s[c0 + 1], 0.f);
                uint32_t byte = SWZ2((uint32_t)(r * 512 + c0 * 2));
                *(uint32_t*)(sm + S_A2 + byte) = ((uint32_t)f2h(v1) << 16) | f2h(v0);
            }
        }
    }
#pragma unroll
    for (int m = 0; m < 2; m++)
#pragma unroll
        for (int n = 0; n < 8; n++)
#pragma unroll
            for (int j = 0; j < 4; j++) acc[m][n][j] = 0.f;

    // ===== layer 2: 4 chunks of k=64, 3-stage, one barrier per chunk =======
    for (int c2 = 0; c2 < 4; ++c2) {
        if (c2 == 0) { CP_WAIT(2); }
        else if (c2 <= 2) { CP_WAIT(1); }
        else { CP_WAIT(0); }
        __syncthreads();   // also orders epilogue-1 A2 writes before reads
        if (c2 == 1) fill2(3);
        int s2 = c2 % 3;
#pragma unroll
        for (int ks = 0; ks < 4; ++ks) {
            uint32_t kg = (uint32_t)(c2 * 64 + ks * 16 + (lane & 3) * 2) * 2;
            uint32_t cb = (uint32_t)(ks * 32 + (lane & 3) * 4);
            uint32_t ah[2][4];
#pragma unroll
            for (int m = 0; m < 2; m++) {
                uint32_t r = (uint32_t)(wm * 32 + m * 16 + (lane >> 2));
                ah[m][0] = *(uint32_t*)(sm + S_A2 + SWZ2(r * 512 + kg));
                ah[m][1] = *(uint32_t*)(sm + S_A2 + SWZ2((r + 8) * 512 + kg));
                ah[m][2] = *(uint32_t*)(sm + S_A2 + SWZ2(r * 512 + kg + 16));
                ah[m][3] = *(uint32_t*)(sm + S_A2 + SWZ2((r + 8) * 512 + kg + 16));
            }
#pragma unroll
            for (int nt = 0; nt < 8; ++nt) {
                uint32_t n = (uint32_t)(wn * 64 + nt * 8 + (lane >> 2));
                uint32_t bh0 = *(uint32_t*)(sm + S_B2(s2) + SWZ(n * 128 + cb));
                uint32_t bh1 = *(uint32_t*)(sm + S_B2(s2) + SWZ(n * 128 + cb + 16));
#pragma unroll
                for (int m = 0; m < 2; m++)
                    mma_h(acc[m][nt], ah[m][0], ah[m][1], ah[m][2], ah[m][3], bh0, bh1);
            }
        }
    }

    // ===== epilogue 2: relu(D+b2), layer-3 dot, reduce, activate, scatter ==
#pragma unroll
    for (int m = 0; m < 2; m++) {
#pragma unroll
        for (int half = 0; half < 2; half++) {
            int rl = wm * 32 + m * 16 + half * 8 + (lane >> 2);
            float p0 = 0.f, p1 = 0.f, p2 = 0.f;
#pragma unroll
            for (int nt = 0; nt < 8; ++nt) {
                int c0 = wn * 64 + nt * 8 + (lane & 3) * 2;
                float v0 = fmaxf(acc[m][nt][half * 2 + 0] + bias2s[c0], 0.f);
                float v1 = fmaxf(acc[m][nt][half * 2 + 1] + bias2s[c0 + 1], 0.f);
                if (is_speed) {
                    p0 += v0 * w3s[c0] + v1 * w3s[c0 + 1];
                } else {
                    p0 += v0 * w3s[c0 * 3]     + v1 * w3s[(c0 + 1) * 3];
                    p1 += v0 * w3s[c0 * 3 + 1] + v1 * w3s[(c0 + 1) * 3 + 1];
                    p2 += v0 * w3s[c0 * 3 + 2] + v1 * w3s[(c0 + 1) * 3 + 2];
                }
            }
#pragma unroll
            for (int d = 1; d < 4; d <<= 1) {
                p0 += __shfl_xor_sync(0xffffffffu, p0, d);
                p1 += __shfl_xor_sync(0xffffffffu, p1, d);
                p2 += __shfl_xor_sync(0xffffffffu, p2, d);
            }
            if ((lane & 3) == 0) {
                if (is_speed) atomicAdd(&sred[rl], p0);
                else {
                    atomicAdd(&sred[rl * 3 + 0], p0);
                    atomicAdd(&sred[rl * 3 + 1], p1);
                    atomicAdd(&sred[rl * 3 + 2], p2);
                }
            }
        }
    }
    __syncthreads();
    if (tid < TM) {
        int orow = rows_s[tid];
        if (is_speed) {
            out[(size_t)Bn * 3 + orow] = sred[tid] + b3s[0];
        } else if (orow >= 0) {
            float s0 = sred[tid * 3 + 0] + b3s[0];
            float s1 = sred[tid * 3 + 1] + b3s[1];
            float s2 = sred[tid * 3 + 2] + b3s[2];
            out[(size_t)orow * 3 + 0] = 1.f / (1.f + expf(-s0));
            out[(size_t)orow * 3 + 1] = 1.f / (1.f + expf(-s1));
            out[(size_t)orow * 3 + 2] = 1.f / (1.f + expf(-s2));
        }
    }
}

// ---------------- launcher (4 launches total) ----------------
extern "C" void kernel_launch(void* const* d_in, const int* in_sizes, int n_in,
                              void* d_out, int out_size) {
    const float* embedding = (const float*)d_in[0];
    const float* speed     = (const float*)d_in[1];
    const int*   command   = (const int*)d_in[2];
    const float* si_W1 = (const float*)d_in[3];
    const float* si_b1 = (const float*)d_in[4];
    const float* si_W2 = (const float*)d_in[5];
    const float* si_b2 = (const float*)d_in[6];
    const float* bW1   = (const float*)d_in[7];
    const float* bb1   = (const float*)d_in[8];
    const float* bW2   = (const float*)d_in[9];
    const float* bb2   = (const float*)d_in[10];
    const float* bW3   = (const float*)d_in[11];
    const float* bb3   = (const float*)d_in[12];
    const float* so_W1 = (const float*)d_in[13];
    const float* so_b1 = (const float*)d_in[14];
    const float* so_W2 = (const float*)d_in[15];
    const float* so_b2 = (const float*)d_in[16];
    const float* so_W3 = (const float*)d_in[17];
    const float* so_b3 = (const float*)d_in[18];
    float* out = (float*)d_out;

    cudaFuncSetAttribute(k_mlp, cudaFuncAttributeMaxDynamicSharedMemorySize, SMEM_TOT);

    k_hist<<<256, 256>>>(command);
    k_scanprep<<<2, 256>>>(si_W1, si_b1, si_W2, si_b2);
    k_prep<<<GA_END, 256>>>(embedding, speed, command, bW1, so_W1, bW2, so_W2);

    int branch_tiles = (Bn + NBn * (TM - 1)) / TM + 1;   // 518
    k_mlp<<<Bn / TM + branch_tiles, 512, SMEM_TOT>>>(
        bb1, bb2, bW3, bb3, so_b1, so_b2, so_W3, so_b3, out);
}